// round 2
// baseline (speedup 1.0000x reference)
#include <cuda_runtime.h>
#include <cstddef>

#define VOCAB 100000
#define EMBED 128
#define STORY 50
#define SENT  64
#define BATCH 64
#define QLEN  16
#define HOPS  3

#define VT     192
#define NBLK_V ((VOCAB + VT - 1) / VT)   // 521
#define PAD    132

// ---------------- scratch (device globals: allocation-free) ----------------
__device__ float g_u[BATCH * EMBED];
__device__ float g_mw[HOPS][BATCH * STORY * EMBED];   // m (pe-weighted sum + TA), tables 0..2
__device__ float g_cs[HOPS][BATCH * STORY * EMBED];   // c (plain sum + TC), tables 1..3
__device__ float g_pmax[BATCH * NBLK_V];
__device__ float g_psum[BATCH * NBLK_V];
__device__ float g_lse[BATCH];

// ---------------- packed fp32x2 FMA (Blackwell) ----------------
__device__ __forceinline__ void ffma2(unsigned long long& d, unsigned long long a,
                                      unsigned long long b) {
    asm("fma.rn.f32x2 %0, %1, %2, %0;" : "+l"(d) : "l"(a), "l"(b));
}

// ---------------- K1: u0 = sum_j A[0][q[b,j]] ----------------
__global__ void k_u0(const int* __restrict__ q, const float* __restrict__ A) {
    const int b = blockIdx.x;
    const int k = threadIdx.x;   // 128
    float acc = 0.f;
#pragma unroll
    for (int j = 0; j < QLEN; ++j) {
        int idx = __ldg(q + b * QLEN + j);
        acc += __ldg(A + (size_t)idx * EMBED + k);
    }
    g_u[b * EMBED + k] = acc;
}

// ---------------- K2: fused gather-reduce per (b,s,h) ----------------
// One gather of table h serves BOTH m of hop h (pe-weighted) and c of hop h-1 (plain).
__global__ void k_gather(const int* __restrict__ x, const float* __restrict__ A,
                         const float* __restrict__ TA, const float* __restrict__ TC) {
    const int bs = blockIdx.x;        // 0..BATCH*STORY-1
    const int h  = blockIdx.y;        // 0..3
    const int s  = bs % STORY;
    const int t  = threadIdx.x;       // 128

    __shared__ int idx[SENT];
    __shared__ float4 redw[4][32];
    __shared__ float4 redp[4][32];

    if (t < SENT) idx[t] = x[bs * SENT + t];
    __syncthreads();

    const float* __restrict__ Ah = A + (size_t)h * VOCAB * EMBED;
    const int c4 = (t & 31) * 4;      // k column (float4)
    const int js = t >> 5;            // j slice 0..3

    const float kf0 = (float)(c4 + 1) * (1.0f / EMBED);
    const float kf1 = (float)(c4 + 2) * (1.0f / EMBED);
    const float kf2 = (float)(c4 + 3) * (1.0f / EMBED);
    const float kf3 = (float)(c4 + 4) * (1.0f / EMBED);

    float4 wp = make_float4(0.f, 0.f, 0.f, 0.f);
    float4 pp = make_float4(0.f, 0.f, 0.f, 0.f);

#pragma unroll
    for (int j = js; j < SENT; j += 4) {
        const float4 a = *(const float4*)(Ah + (size_t)idx[j] * EMBED + c4);
        const float fj = (float)(j + 1) * (1.0f / SENT);
        const float g  = 1.0f - 2.0f * fj;
        const float base = 1.0f - fj;
        wp.x = fmaf(a.x, fmaf(-kf0, g, base), wp.x);
        wp.y = fmaf(a.y, fmaf(-kf1, g, base), wp.y);
        wp.z = fmaf(a.z, fmaf(-kf2, g, base), wp.z);
        wp.w = fmaf(a.w, fmaf(-kf3, g, base), wp.w);
        pp.x += a.x; pp.y += a.y; pp.z += a.z; pp.w += a.w;
    }

    redw[js][t & 31] = wp;
    redp[js][t & 31] = pp;
    __syncthreads();

    if (t < 32) {
        float4 w = redw[0][t], p = redp[0][t];
#pragma unroll
        for (int r = 1; r < 4; ++r) {
            float4 w2 = redw[r][t], p2 = redp[r][t];
            w.x += w2.x; w.y += w2.y; w.z += w2.z; w.w += w2.w;
            p.x += p2.x; p.y += p2.y; p.z += p2.z; p.w += p2.w;
        }
        const int k0 = t * 4;
        if (h < HOPS) {
            const float4 ta4 = *(const float4*)(TA + s * EMBED + k0);
            w.x += ta4.x; w.y += ta4.y; w.z += ta4.z; w.w += ta4.w;
            *(float4*)(g_mw[h] + (size_t)bs * EMBED + k0) = w;
        }
        if (h > 0) {
            const float4 tc4 = *(const float4*)(TC + s * EMBED + k0);
            p.x += tc4.x; p.y += tc4.y; p.z += tc4.z; p.w += tc4.w;
            *(float4*)(g_cs[h - 1] + (size_t)bs * EMBED + k0) = p;
        }
    }
}

// ---------------- K3: 3 hops, per-batch independent ----------------
__global__ void k_hops() {
    const int b = blockIdx.x;
    const int t = threadIdx.x;     // 128
    const int w = t >> 5, lane = t & 31;

    __shared__ float u[EMBED];
    __shared__ float sc[STORY];

    u[t] = g_u[b * EMBED + t];
    __syncthreads();

    for (int h = 0; h < HOPS; ++h) {
        const float* __restrict__ m = g_mw[h] + (size_t)b * STORY * EMBED;
        const float* __restrict__ c = g_cs[h] + (size_t)b * STORY * EMBED;

        // scores[s] = m[s] . u
        for (int s = w; s < STORY; s += 4) {
            const float* mr = m + s * EMBED;
            float d = mr[lane]      * u[lane]
                    + mr[lane + 32] * u[lane + 32]
                    + mr[lane + 64] * u[lane + 64]
                    + mr[lane + 96] * u[lane + 96];
#pragma unroll
            for (int o = 16; o; o >>= 1) d += __shfl_xor_sync(0xffffffffu, d, o);
            if (lane == 0) sc[s] = d;
        }
        __syncthreads();

        // softmax over STORY=50 (warp 0)
        if (t < 32) {
            float v0 = sc[t];
            float v1 = (t + 32 < STORY) ? sc[t + 32] : -3.4e38f;
            float mx = fmaxf(v0, v1);
#pragma unroll
            for (int o = 16; o; o >>= 1) mx = fmaxf(mx, __shfl_xor_sync(0xffffffffu, mx, o));
            float e0 = __expf(v0 - mx);
            float e1 = (t + 32 < STORY) ? __expf(v1 - mx) : 0.f;
            float sum = e0 + e1;
#pragma unroll
            for (int o = 16; o; o >>= 1) sum += __shfl_xor_sync(0xffffffffu, sum, o);
            float inv = 1.0f / sum;
            sc[t] = e0 * inv;
            if (t + 32 < STORY) sc[t + 32] = e1 * inv;
        }
        __syncthreads();

        // u += sum_s p[s] * c[s]
        float acc = u[t];
        for (int s = 0; s < STORY; ++s)
            acc = fmaf(sc[s], c[s * EMBED + t], acc);
        u[t] = acc;
        __syncthreads();
    }
    g_u[b * EMBED + t] = u[t];
}

// ---------------- K4a: logits = u @ A3^T, fused per-block max/sumexp ----------------
// Thread tile 8b x 6v, k-step 2 via fp32x2. LDS return <= FMA issue -> FMA-bound.
#define SMEM_LOGITS ((BATCH * EMBED + VT * PAD) * 4)   // 32768 + 101376 = 134144 B

__global__ void __launch_bounds__(256) k_logits(const float* __restrict__ A3,
                                                float* __restrict__ out) {
    extern __shared__ float sh[];
    float* sU = sh;                   // [64][128]
    float* sA = sh + BATCH * EMBED;   // [192][132] padded

    const int t   = threadIdx.x;      // 256
    const int blk = blockIdx.x;
    const int v0  = blk * VT;

#pragma unroll
    for (int i = t; i < BATCH * EMBED / 4; i += 256)
        ((float4*)sU)[i] = ((const float4*)g_u)[i];

    for (int i = t; i < VT * 32; i += 256) {
        const int r = i >> 5, c = i & 31;
        const int v = v0 + r;
        float4 val = make_float4(0.f, 0.f, 0.f, 0.f);
        if (v < VOCAB) val = *(const float4*)(A3 + (size_t)v * EMBED + c * 4);
        *(float4*)(sA + r * PAD + c * 4) = val;
    }
    __syncthreads();

    const int tx = t & 31, ty = t >> 5;
    // thread computes b = ty*8 + i (i<8), v = v0 + tx + j*32 (j<6)

    unsigned long long acc[8][6];
#pragma unroll
    for (int i = 0; i < 8; ++i)
#pragma unroll
        for (int j = 0; j < 6; ++j) acc[i][j] = 0ull;

    const float* uBase = sU + ty * 8 * EMBED;
    const float* aBase = sA + tx * PAD;

#pragma unroll 2
    for (int k = 0; k < EMBED; k += 2) {
        unsigned long long aa[6];
#pragma unroll
        for (int j = 0; j < 6; ++j)
            aa[j] = *(const unsigned long long*)(aBase + j * 32 * PAD + k);
#pragma unroll
        for (int i = 0; i < 8; ++i) {
            const unsigned long long uu =
                *(const unsigned long long*)(uBase + i * EMBED + k);
#pragma unroll
            for (int j = 0; j < 6; ++j) ffma2(acc[i][j], uu, aa[j]);
        }
    }

    float lg[8][6];
#pragma unroll
    for (int i = 0; i < 8; ++i)
#pragma unroll
        for (int j = 0; j < 6; ++j) {
            const float2 f = *(float2*)&acc[i][j];
            lg[i][j] = f.x + f.y;
        }

    // store logits (warp-coalesced STG.32) + mask invalid v
#pragma unroll
    for (int i = 0; i < 8; ++i) {
        const int b = ty * 8 + i;
#pragma unroll
        for (int j = 0; j < 6; ++j) {
            const int v = v0 + tx + j * 32;
            if (v < VOCAB) out[(size_t)b * VOCAB + v] = lg[i][j];
            else           lg[i][j] = -3.4e38f;
        }
    }

    // per-b block partials (each warp owns 8 distinct b; shfl across 32 lanes)
#pragma unroll
    for (int i = 0; i < 8; ++i) {
        float m = lg[i][0];
#pragma unroll
        for (int j = 1; j < 6; ++j) m = fmaxf(m, lg[i][j]);
#pragma unroll
        for (int o = 16; o; o >>= 1) m = fmaxf(m, __shfl_xor_sync(0xffffffffu, m, o));
        float s = 0.f;
#pragma unroll
        for (int j = 0; j < 6; ++j) s += __expf(lg[i][j] - m);
#pragma unroll
        for (int o = 16; o; o >>= 1) s += __shfl_xor_sync(0xffffffffu, s, o);
        if (tx == 0) {
            const int b = ty * 8 + i;
            g_pmax[b * NBLK_V + blk] = m;
            g_psum[b * NBLK_V + blk] = s;
        }
    }
}

// ---------------- K4b: per-row logsumexp reduce ----------------
__global__ void k_lse() {
    const int b = blockIdx.x, t = threadIdx.x;   // 256
    float m = -3.4e38f, s = 0.f;
    for (int i = t; i < NBLK_V; i += 256) {
        const float bm = g_pmax[b * NBLK_V + i];
        const float bs = g_psum[b * NBLK_V + i];
        if (bm > m) { s = s * __expf(m - bm) + bs; m = bm; }
        else        { s += bs * __expf(bm - m); }
    }
    __shared__ float sm[256], ss[256];
    sm[t] = m; ss[t] = s;
    __syncthreads();
    for (int o = 128; o; o >>= 1) {
        if (t < o) {
            const float m2 = sm[t + o], s2 = ss[t + o];
            if (m2 > sm[t]) { ss[t] = ss[t] * __expf(sm[t] - m2) + s2; sm[t] = m2; }
            else            { ss[t] += s2 * __expf(m2 - sm[t]); }
        }
        __syncthreads();
    }
    if (t == 0) g_lse[b] = sm[0] + logf(ss[0]);
}

// ---------------- K4c: finalize out = logit - lse[b] ----------------
__global__ void k_final(float* __restrict__ out) {
    const int i = blockIdx.x * 256 + threadIdx.x;
    if (i >= BATCH * VOCAB / 4) return;
    const int b = (i * 4) / VOCAB;
    const float lse = __ldg(g_lse + b);
    float4 v = ((float4*)out)[i];
    v.x -= lse; v.y -= lse; v.z -= lse; v.w -= lse;
    ((float4*)out)[i] = v;
}

// ---------------- launch ----------------
extern "C" void kernel_launch(void* const* d_in, const int* in_sizes, int n_in,
                              void* d_out, int out_size) {
    const int*   x  = (const int*)d_in[0];
    const int*   q  = (const int*)d_in[1];
    const float* A  = (const float*)d_in[2];
    const float* TA = (const float*)d_in[3];
    const float* TC = (const float*)d_in[4];
    float* out = (float*)d_out;

    k_u0<<<BATCH, EMBED>>>(q, A);
    k_gather<<<dim3(BATCH * STORY, HOPS + 1), 128>>>(x, A, TA, TC);
    k_hops<<<BATCH, EMBED>>>();

    cudaFuncSetAttribute(k_logits, cudaFuncAttributeMaxDynamicSharedMemorySize, SMEM_LOGITS);
    k_logits<<<NBLK_V, 256, SMEM_LOGITS>>>(A + (size_t)HOPS * VOCAB * EMBED, out);

    k_lse<<<BATCH, 256>>>();
    k_final<<<(BATCH * VOCAB / 4 + 255) / 256, 256>>>(out);
}

// round 3
// speedup vs baseline: 1.0948x; 1.0948x over previous
#include <cuda_runtime.h>
#include <cstddef>

#define VOCAB 100000
#define EMBED 128
#define STORY 50
#define SENT  64
#define BATCH 64
#define QLEN  16
#define HOPS  3

#define VT     128
#define NBLK_V ((VOCAB + VT - 1) / VT)   // 782
#define PAD    132

// ---------------- scratch (device globals: allocation-free) ----------------
__device__ float g_u[BATCH * EMBED];
__device__ float g_mw[HOPS][BATCH * STORY * EMBED];   // m (pe-weighted sum + TA)
__device__ float g_cs[HOPS][BATCH * STORY * EMBED];   // c (plain sum + TC)
__device__ float g_pmax[BATCH * NBLK_V];
__device__ float g_psum[BATCH * NBLK_V];
__device__ float g_lse[BATCH];

// ---------------- packed fp32x2 FMA (Blackwell) ----------------
__device__ __forceinline__ void ffma2(unsigned long long& d, unsigned long long a,
                                      unsigned long long b) {
    asm("fma.rn.f32x2 %0, %1, %2, %0;" : "+l"(d) : "l"(a), "l"(b));
}

// ---------------- K1: u0 = sum_j A[0][q[b,j]] ----------------
__global__ void k_u0(const int* __restrict__ q, const float* __restrict__ A) {
    const int b = blockIdx.x;
    const int k = threadIdx.x;   // 128
    float acc = 0.f;
#pragma unroll
    for (int j = 0; j < QLEN; ++j) {
        int idx = __ldg(q + b * QLEN + j);
        acc += __ldg(A + (size_t)idx * EMBED + k);
    }
    g_u[b * EMBED + k] = acc;
}

// ---------------- K2: fused gather-reduce, one warp per (bs,h) ----------------
// One gather of table h serves BOTH m of hop h (pe-weighted) and c of hop h-1.
// Warp-private accumulation: no inter-warp reduce, full-warp float4 stores.
__global__ void __launch_bounds__(128) k_gather(const int* __restrict__ x,
                                                const float* __restrict__ A,
                                                const float* __restrict__ TA,
                                                const float* __restrict__ TC) {
    const int t    = threadIdx.x;
    const int w    = t >> 5, lane = t & 31;
    const int bs   = blockIdx.x * 4 + w;
    const int h    = blockIdx.y;
    const int s    = bs % STORY;

    __shared__ int idx[4][SENT];
    ((int*)idx)[t]       = x[blockIdx.x * 4 * SENT + t];
    ((int*)idx)[t + 128] = x[blockIdx.x * 4 * SENT + t + 128];
    __syncthreads();

    const float* __restrict__ Ah = A + (size_t)h * VOCAB * EMBED;
    const int c4 = lane * 4;

    const float kf0 = (float)(c4 + 1) * (1.0f / EMBED);
    const float kf1 = (float)(c4 + 2) * (1.0f / EMBED);
    const float kf2 = (float)(c4 + 3) * (1.0f / EMBED);
    const float kf3 = (float)(c4 + 4) * (1.0f / EMBED);

    float4 wp = make_float4(0.f, 0.f, 0.f, 0.f);
    float4 pp = make_float4(0.f, 0.f, 0.f, 0.f);

#pragma unroll 16
    for (int j = 0; j < SENT; ++j) {
        const float4 a = *(const float4*)(Ah + (size_t)idx[w][j] * EMBED + c4);
        const float fj   = (float)(j + 1) * (1.0f / SENT);
        const float g    = 1.0f - 2.0f * fj;
        const float base = 1.0f - fj;
        wp.x = fmaf(a.x, fmaf(-kf0, g, base), wp.x);
        wp.y = fmaf(a.y, fmaf(-kf1, g, base), wp.y);
        wp.z = fmaf(a.z, fmaf(-kf2, g, base), wp.z);
        wp.w = fmaf(a.w, fmaf(-kf3, g, base), wp.w);
        pp.x += a.x; pp.y += a.y; pp.z += a.z; pp.w += a.w;
    }

    if (h < HOPS) {
        const float4 ta4 = *(const float4*)(TA + s * EMBED + c4);
        wp.x += ta4.x; wp.y += ta4.y; wp.z += ta4.z; wp.w += ta4.w;
        *(float4*)(g_mw[h] + (size_t)bs * EMBED + c4) = wp;
    }
    if (h > 0) {
        const float4 tc4 = *(const float4*)(TC + s * EMBED + c4);
        pp.x += tc4.x; pp.y += tc4.y; pp.z += tc4.z; pp.w += tc4.w;
        *(float4*)(g_cs[h - 1] + (size_t)bs * EMBED + c4) = pp;
    }
}

// ---------------- K3: 3 hops, per-batch independent ----------------
__global__ void k_hops() {
    const int b = blockIdx.x;
    const int t = threadIdx.x;     // 128
    const int w = t >> 5, lane = t & 31;

    __shared__ float u[EMBED];
    __shared__ float sc[STORY];

    u[t] = g_u[b * EMBED + t];
    __syncthreads();

    for (int h = 0; h < HOPS; ++h) {
        const float* __restrict__ m = g_mw[h] + (size_t)b * STORY * EMBED;
        const float* __restrict__ c = g_cs[h] + (size_t)b * STORY * EMBED;

        for (int s = w; s < STORY; s += 4) {
            const float* mr = m + s * EMBED;
            float d = mr[lane]      * u[lane]
                    + mr[lane + 32] * u[lane + 32]
                    + mr[lane + 64] * u[lane + 64]
                    + mr[lane + 96] * u[lane + 96];
#pragma unroll
            for (int o = 16; o; o >>= 1) d += __shfl_xor_sync(0xffffffffu, d, o);
            if (lane == 0) sc[s] = d;
        }
        __syncthreads();

        if (t < 32) {
            float v0 = sc[t];
            float v1 = (t + 32 < STORY) ? sc[t + 32] : -3.4e38f;
            float mx = fmaxf(v0, v1);
#pragma unroll
            for (int o = 16; o; o >>= 1) mx = fmaxf(mx, __shfl_xor_sync(0xffffffffu, mx, o));
            float e0 = __expf(v0 - mx);
            float e1 = (t + 32 < STORY) ? __expf(v1 - mx) : 0.f;
            float sum = e0 + e1;
#pragma unroll
            for (int o = 16; o; o >>= 1) sum += __shfl_xor_sync(0xffffffffu, sum, o);
            float inv = 1.0f / sum;
            sc[t] = e0 * inv;
            if (t + 32 < STORY) sc[t + 32] = e1 * inv;
        }
        __syncthreads();

        float acc = u[t];
        for (int s = 0; s < STORY; ++s)
            acc = fmaf(sc[s], c[s * EMBED + t], acc);
        u[t] = acc;
        __syncthreads();
    }
    g_u[b * EMBED + t] = u[t];
}

// ---------------- K4a: logits = u @ A3^T, fused per-block max/sumexp ----------------
// Tile 8b x 4v per thread, k-step 4 (LDS.128). Per 4k per warp:
//   FMA = 32 SM-cyc  >  LDS = 4*4 (A distinct) + 8 (u broadcast) = 24 cyc.
// acc = 64 regs; VT=128 -> smem ~100KB -> 2 blocks/SM (16 warps).
#define SMEM_LOGITS ((BATCH * EMBED + VT * PAD) * 4)   // 32768 + 67584 = 100352 B

__global__ void __launch_bounds__(256, 2) k_logits(const float* __restrict__ A3,
                                                   float* __restrict__ out) {
    extern __shared__ float sh[];
    float* sU = sh;                   // [64][128]
    float* sA = sh + BATCH * EMBED;   // [128][132] padded

    const int t   = threadIdx.x;      // 256
    const int blk = blockIdx.x;
    const int v0  = blk * VT;

#pragma unroll
    for (int i = t; i < BATCH * EMBED / 4; i += 256)
        ((float4*)sU)[i] = ((const float4*)g_u)[i];

#pragma unroll
    for (int i = t; i < VT * 32; i += 256) {
        const int r = i >> 5, c = i & 31;
        const int v = v0 + r;
        float4 val = make_float4(0.f, 0.f, 0.f, 0.f);
        if (v < VOCAB) val = *(const float4*)(A3 + (size_t)v * EMBED + c * 4);
        *(float4*)(sA + r * PAD + c * 4) = val;
    }
    __syncthreads();

    const int tx = t & 31, ty = t >> 5;
    // thread: b = ty*8 + i (i<8), v = v0 + tx + j*32 (j<4)

    unsigned long long acc[8][4];
#pragma unroll
    for (int i = 0; i < 8; ++i)
#pragma unroll
        for (int j = 0; j < 4; ++j) acc[i][j] = 0ull;

    const float* uBase = sU + ty * 8 * EMBED;
    const float* aBase = sA + tx * PAD;

#pragma unroll 4
    for (int k = 0; k < EMBED; k += 4) {
        ulonglong2 aa[4];
#pragma unroll
        for (int j = 0; j < 4; ++j)
            aa[j] = *(const ulonglong2*)(aBase + j * 32 * PAD + k);
#pragma unroll
        for (int i = 0; i < 8; ++i) {
            const ulonglong2 uu = *(const ulonglong2*)(uBase + i * EMBED + k);
#pragma unroll
            for (int j = 0; j < 4; ++j) {
                ffma2(acc[i][j], uu.x, aa[j].x);
                ffma2(acc[i][j], uu.y, aa[j].y);
            }
        }
    }

    float lg[8][4];
#pragma unroll
    for (int i = 0; i < 8; ++i)
#pragma unroll
        for (int j = 0; j < 4; ++j) {
            const float2 f = *(float2*)&acc[i][j];
            lg[i][j] = f.x + f.y;
        }

    // store logits (warp-coalesced STG.32) + mask invalid v
#pragma unroll
    for (int i = 0; i < 8; ++i) {
        const int b = ty * 8 + i;
#pragma unroll
        for (int j = 0; j < 4; ++j) {
            const int v = v0 + tx + j * 32;
            if (v < VOCAB) out[(size_t)b * VOCAB + v] = lg[i][j];
            else           lg[i][j] = -3.4e38f;
        }
    }

    // per-b block partials (each warp owns 8 distinct b)
#pragma unroll
    for (int i = 0; i < 8; ++i) {
        float m = lg[i][0];
#pragma unroll
        for (int j = 1; j < 4; ++j) m = fmaxf(m, lg[i][j]);
#pragma unroll
        for (int o = 16; o; o >>= 1) m = fmaxf(m, __shfl_xor_sync(0xffffffffu, m, o));
        float s = 0.f;
#pragma unroll
        for (int j = 0; j < 4; ++j) s += __expf(lg[i][j] - m);
#pragma unroll
        for (int o = 16; o; o >>= 1) s += __shfl_xor_sync(0xffffffffu, s, o);
        if (tx == 0) {
            const int b = ty * 8 + i;
            g_pmax[b * NBLK_V + blk] = m;
            g_psum[b * NBLK_V + blk] = s;
        }
    }
}

// ---------------- K4b: per-row logsumexp reduce ----------------
__global__ void k_lse() {
    const int b = blockIdx.x, t = threadIdx.x;   // 256
    float m = -3.4e38f, s = 0.f;
    for (int i = t; i < NBLK_V; i += 256) {
        const float bm = g_pmax[b * NBLK_V + i];
        const float bs = g_psum[b * NBLK_V + i];
        if (bm > m) { s = s * __expf(m - bm) + bs; m = bm; }
        else        { s += bs * __expf(bm - m); }
    }
    __shared__ float sm[256], ss[256];
    sm[t] = m; ss[t] = s;
    __syncthreads();
    for (int o = 128; o; o >>= 1) {
        if (t < o) {
            const float m2 = sm[t + o], s2 = ss[t + o];
            if (m2 > sm[t]) { ss[t] = ss[t] * __expf(sm[t] - m2) + s2; sm[t] = m2; }
            else            { ss[t] += s2 * __expf(m2 - sm[t]); }
        }
        __syncthreads();
    }
    if (t == 0) g_lse[b] = sm[0] + logf(ss[0]);
}

// ---------------- K4c: finalize out = logit - lse[b] ----------------
__global__ void k_final(float* __restrict__ out) {
    const int i = blockIdx.x * 256 + threadIdx.x;
    if (i >= BATCH * VOCAB / 4) return;
    const int b = (i * 4) / VOCAB;
    const float lse = __ldg(g_lse + b);
    float4 v = ((float4*)out)[i];
    v.x -= lse; v.y -= lse; v.z -= lse; v.w -= lse;
    ((float4*)out)[i] = v;
}

// ---------------- launch ----------------
extern "C" void kernel_launch(void* const* d_in, const int* in_sizes, int n_in,
                              void* d_out, int out_size) {
    const int*   x  = (const int*)d_in[0];
    const int*   q  = (const int*)d_in[1];
    const float* A  = (const float*)d_in[2];
    const float* TA = (const float*)d_in[3];
    const float* TC = (const float*)d_in[4];
    float* out = (float*)d_out;

    k_u0<<<BATCH, EMBED>>>(q, A);
    k_gather<<<dim3(BATCH * STORY / 4, HOPS + 1), 128>>>(x, A, TA, TC);
    k_hops<<<BATCH, EMBED>>>();

    cudaFuncSetAttribute(k_logits, cudaFuncAttributeMaxDynamicSharedMemorySize, SMEM_LOGITS);
    k_logits<<<NBLK_V, 256, SMEM_LOGITS>>>(A + (size_t)HOPS * VOCAB * EMBED, out);

    k_lse<<<BATCH, 256>>>();
    k_final<<<(BATCH * VOCAB / 4 + 255) / 256, 256>>>(out);
}

// round 5
// speedup vs baseline: 1.2937x; 1.1817x over previous
#include <cuda_runtime.h>
#include <cstddef>
#include <cstdint>

#define VOCAB 100000
#define EMBED 128
#define STORY 50
#define SENT  64
#define BATCH 64
#define QLEN  16
#define HOPS  3

#define VT     128
#define NBLK_V ((VOCAB + VT - 1) / VT)   // 782
#define PAD    132

// ---------------- scratch (device globals: allocation-free) ----------------
__device__ float g_u[BATCH * EMBED];
__device__ float g_mw[HOPS][BATCH * STORY * EMBED];
__device__ float g_cs[HOPS][BATCH * STORY * EMBED];
__device__ float g_pmax[BATCH * NBLK_V];
__device__ float g_psum[BATCH * NBLK_V];
__device__ float g_lse[BATCH];

// ---------------- tf32 helpers ----------------
__device__ __forceinline__ uint32_t to_tf32(float x) {
    uint32_t r;
    asm("cvt.rna.tf32.f32 %0, %1;" : "=r"(r) : "f"(x));
    return r;
}
__device__ __forceinline__ void mma_tf32(float d[4], const uint32_t a[4],
                                         uint32_t b0, uint32_t b1) {
    asm volatile(
        "mma.sync.aligned.m16n8k8.row.col.f32.tf32.tf32.f32 "
        "{%0,%1,%2,%3}, {%4,%5,%6,%7}, {%8,%9}, {%0,%1,%2,%3};"
        : "+f"(d[0]), "+f"(d[1]), "+f"(d[2]), "+f"(d[3])
        : "r"(a[0]), "r"(a[1]), "r"(a[2]), "r"(a[3]), "r"(b0), "r"(b1));
}

// ---------------- K1: u0 = sum_j A[0][q[b,j]] ----------------
__global__ void k_u0(const int* __restrict__ q, const float* __restrict__ A) {
    const int b = blockIdx.x;
    const int k = threadIdx.x;   // 128
    float acc = 0.f;
#pragma unroll
    for (int j = 0; j < QLEN; ++j) {
        int idx = __ldg(q + b * QLEN + j);
        acc += __ldg(A + (size_t)idx * EMBED + k);
    }
    g_u[b * EMBED + k] = acc;
}

// ---------------- K2: fused gather-reduce, one warp per (bs,h) ----------------
__global__ void __launch_bounds__(128) k_gather(const int* __restrict__ x,
                                                const float* __restrict__ A,
                                                const float* __restrict__ TA,
                                                const float* __restrict__ TC) {
    const int t    = threadIdx.x;
    const int w    = t >> 5, lane = t & 31;
    const int bs   = blockIdx.x * 4 + w;
    const int h    = blockIdx.y;
    const int s    = bs % STORY;

    __shared__ int idx[4][SENT];
    ((int*)idx)[t]       = x[blockIdx.x * 4 * SENT + t];
    ((int*)idx)[t + 128] = x[blockIdx.x * 4 * SENT + t + 128];
    __syncthreads();

    const float* __restrict__ Ah = A + (size_t)h * VOCAB * EMBED;
    const int c4 = lane * 4;

    const float kf0 = (float)(c4 + 1) * (1.0f / EMBED);
    const float kf1 = (float)(c4 + 2) * (1.0f / EMBED);
    const float kf2 = (float)(c4 + 3) * (1.0f / EMBED);
    const float kf3 = (float)(c4 + 4) * (1.0f / EMBED);

    float4 wp = make_float4(0.f, 0.f, 0.f, 0.f);
    float4 pp = make_float4(0.f, 0.f, 0.f, 0.f);

#pragma unroll 16
    for (int j = 0; j < SENT; ++j) {
        const float4 a = *(const float4*)(Ah + (size_t)idx[w][j] * EMBED + c4);
        const float fj   = (float)(j + 1) * (1.0f / SENT);
        const float g    = 1.0f - 2.0f * fj;
        const float base = 1.0f - fj;
        wp.x = fmaf(a.x, fmaf(-kf0, g, base), wp.x);
        wp.y = fmaf(a.y, fmaf(-kf1, g, base), wp.y);
        wp.z = fmaf(a.z, fmaf(-kf2, g, base), wp.z);
        wp.w = fmaf(a.w, fmaf(-kf3, g, base), wp.w);
        pp.x += a.x; pp.y += a.y; pp.z += a.z; pp.w += a.w;
    }

    if (h < HOPS) {
        const float4 ta4 = *(const float4*)(TA + s * EMBED + c4);
        wp.x += ta4.x; wp.y += ta4.y; wp.z += ta4.z; wp.w += ta4.w;
        *(float4*)(g_mw[h] + (size_t)bs * EMBED + c4) = wp;
    }
    if (h > 0) {
        const float4 tc4 = *(const float4*)(TC + s * EMBED + c4);
        pp.x += tc4.x; pp.y += tc4.y; pp.z += tc4.z; pp.w += tc4.w;
        *(float4*)(g_cs[h - 1] + (size_t)bs * EMBED + c4) = pp;
    }
}

// ---------------- K3: 3 hops, per-batch independent ----------------
__global__ void k_hops() {
    const int b = blockIdx.x;
    const int t = threadIdx.x;     // 128
    const int w = t >> 5, lane = t & 31;

    __shared__ float u[EMBED];
    __shared__ float sc[STORY];

    u[t] = g_u[b * EMBED + t];
    __syncthreads();

    for (int h = 0; h < HOPS; ++h) {
        const float* __restrict__ m = g_mw[h] + (size_t)b * STORY * EMBED;
        const float* __restrict__ c = g_cs[h] + (size_t)b * STORY * EMBED;

        for (int s = w; s < STORY; s += 4) {
            const float* mr = m + s * EMBED;
            float d = mr[lane]      * u[lane]
                    + mr[lane + 32] * u[lane + 32]
                    + mr[lane + 64] * u[lane + 64]
                    + mr[lane + 96] * u[lane + 96];
#pragma unroll
            for (int o = 16; o; o >>= 1) d += __shfl_xor_sync(0xffffffffu, d, o);
            if (lane == 0) sc[s] = d;
        }
        __syncthreads();

        if (t < 32) {
            float v0 = sc[t];
            float v1 = (t + 32 < STORY) ? sc[t + 32] : -3.4e38f;
            float mx = fmaxf(v0, v1);
#pragma unroll
            for (int o = 16; o; o >>= 1) mx = fmaxf(mx, __shfl_xor_sync(0xffffffffu, mx, o));
            float e0 = __expf(v0 - mx);
            float e1 = (t + 32 < STORY) ? __expf(v1 - mx) : 0.f;
            float sum = e0 + e1;
#pragma unroll
            for (int o = 16; o; o >>= 1) sum += __shfl_xor_sync(0xffffffffu, sum, o);
            float inv = 1.0f / sum;
            sc[t] = e0 * inv;
            if (t + 32 < STORY) sc[t + 32] = e1 * inv;
        }
        __syncthreads();

        float acc = u[t];
        for (int s = 0; s < STORY; ++s)
            acc = fmaf(sc[s], c[s * EMBED + t], acc);
        u[t] = acc;
        __syncthreads();
    }
    g_u[b * EMBED + t] = u[t];
}

// ---------------- K4a: logits via mma.sync tf32 (HMMA) ----------------
// Block: 128 threads (4 warps). Tile: VT=128 v x 64 b, K=128.
// Warp tile: 32 b (2 m-tiles) x 64 v (8 n-tiles). u = mma-A (row), A3 = mma-B (col).
// smem: sU[64][132] tf32, sA[128][132] tf32, redm[128], reds[128] -> 102400 B.
#define SU_F  (BATCH * PAD)           // 8448
#define SA_F  (VT * PAD)              // 16896
#define SMEM_LOGITS ((SU_F + SA_F + 256) * 4)   // 102400

__global__ void __launch_bounds__(128, 2) k_logits(const float* __restrict__ A3,
                                                   float* __restrict__ out) {
    extern __shared__ float sh[];
    float* sU   = sh;
    float* sA   = sh + SU_F;
    float* redm = sh + SU_F + SA_F;     // [2][64]
    float* reds = redm + 128;           // [2][64]

    const int t = threadIdx.x, wid = t >> 5, lane = t & 31;
    const int g = lane >> 2, t4 = lane & 3;
    const int wv = wid & 1, wb = wid >> 1;
    const int blk = blockIdx.x, v0 = blk * VT;

    // ---- load tiles, converting to tf32 (rna) once ----
    const float4* srcU = (const float4*)g_u;
#pragma unroll
    for (int i = t; i < BATCH * 32; i += 128) {
        const int r = i >> 5, c = i & 31;
        const float4 v = srcU[i];
        uint4 w = make_uint4(to_tf32(v.x), to_tf32(v.y), to_tf32(v.z), to_tf32(v.w));
        *(uint4*)(sU + r * PAD + c * 4) = w;
    }
    const float4* srcA = (const float4*)A3;
#pragma unroll
    for (int i = t; i < VT * 32; i += 128) {
        const int r = i >> 5, c = i & 31;
        int row = v0 + r; if (row > VOCAB - 1) row = VOCAB - 1;
        const float4 v = srcA[(size_t)row * 32 + c];
        uint4 w = make_uint4(to_tf32(v.x), to_tf32(v.y), to_tf32(v.z), to_tf32(v.w));
        *(uint4*)(sA + r * PAD + c * 4) = w;
    }
    __syncthreads();

    // ---- mainloop ----
    float acc[2][8][4];
#pragma unroll
    for (int m = 0; m < 2; ++m)
#pragma unroll
        for (int n = 0; n < 8; ++n)
#pragma unroll
            for (int e = 0; e < 4; ++e) acc[m][n][e] = 0.f;

    const uint32_t* Ub = (const uint32_t*)sU + (wb * 32 + g) * PAD + t4;
    const uint32_t* Bb = (const uint32_t*)sA + (wv * 64 + g) * PAD + t4;

#pragma unroll 4
    for (int ks = 0; ks < 16; ++ks) {
        const int k0 = ks * 8;
        uint32_t a[2][4];
#pragma unroll
        for (int m = 0; m < 2; ++m) {
            const uint32_t* p = Ub + m * 16 * PAD + k0;
            a[m][0] = p[0];
            a[m][1] = p[8 * PAD];
            a[m][2] = p[4];
            a[m][3] = p[8 * PAD + 4];
        }
#pragma unroll
        for (int n = 0; n < 8; ++n) {
            const uint32_t* p = Bb + n * 8 * PAD + k0;
            const uint32_t b0 = p[0], b1 = p[4];
            mma_tf32(acc[0][n], a[0], b0, b1);
            mma_tf32(acc[1][n], a[1], b0, b1);
        }
    }

    // ---- store logits (float2, v-contiguous) ----
#pragma unroll
    for (int m = 0; m < 2; ++m) {
        const int b0r = wb * 32 + m * 16 + g;
#pragma unroll
        for (int n = 0; n < 8; ++n) {
            const int vv = v0 + wv * 64 + n * 8 + t4 * 2;
            if (vv < VOCAB) {
                *(float2*)(out + (size_t)b0r * VOCAB + vv) =
                    make_float2(acc[m][n][0], acc[m][n][1]);
                *(float2*)(out + (size_t)(b0r + 8) * VOCAB + vv) =
                    make_float2(acc[m][n][2], acc[m][n][3]);
            }
        }
    }

    // ---- per-b block max ----
#pragma unroll
    for (int m = 0; m < 2; ++m)
#pragma unroll
        for (int half = 0; half < 2; ++half) {
            float mx = -3.4e38f;
#pragma unroll
            for (int n = 0; n < 8; ++n) {
                const int vv = v0 + wv * 64 + n * 8 + t4 * 2;
                if (vv < VOCAB)
                    mx = fmaxf(mx, fmaxf(acc[m][n][half * 2], acc[m][n][half * 2 + 1]));
            }
            mx = fmaxf(mx, __shfl_xor_sync(0xffffffffu, mx, 1));
            mx = fmaxf(mx, __shfl_xor_sync(0xffffffffu, mx, 2));
            if (t4 == 0) redm[wv * 64 + wb * 32 + m * 16 + half * 8 + g] = mx;
        }
    __syncthreads();

    // ---- per-b block sumexp ----
#pragma unroll
    for (int m = 0; m < 2; ++m)
#pragma unroll
        for (int half = 0; half < 2; ++half) {
            const int bb = wb * 32 + m * 16 + half * 8 + g;
            const float bm = fmaxf(redm[bb], redm[64 + bb]);
            float e = 0.f;
#pragma unroll
            for (int n = 0; n < 8; ++n) {
                const int vv = v0 + wv * 64 + n * 8 + t4 * 2;
                if (vv < VOCAB)
                    e += __expf(acc[m][n][half * 2] - bm) +
                         __expf(acc[m][n][half * 2 + 1] - bm);
            }
            e += __shfl_xor_sync(0xffffffffu, e, 1);
            e += __shfl_xor_sync(0xffffffffu, e, 2);
            if (t4 == 0) reds[wv * 64 + bb] = e;
        }
    __syncthreads();

    if (t < BATCH) {
        const float bm = fmaxf(redm[t], redm[64 + t]);
        const float bs = reds[t] + reds[64 + t];
        g_pmax[t * NBLK_V + blk] = bm;
        g_psum[t * NBLK_V + blk] = bs;
    }
}

// ---------------- K4b: per-row logsumexp reduce ----------------
__global__ void k_lse() {
    const int b = blockIdx.x, t = threadIdx.x;   // 256
    float m = -3.4e38f, s = 0.f;
    for (int i = t; i < NBLK_V; i += 256) {
        const float bm = g_pmax[b * NBLK_V + i];
        const float bs = g_psum[b * NBLK_V + i];
        if (bm > m) { s = s * __expf(m - bm) + bs; m = bm; }
        else        { s += bs * __expf(bm - m); }
    }
    __shared__ float sm[256], ss[256];
    sm[t] = m; ss[t] = s;
    __syncthreads();
    for (int o = 128; o; o >>= 1) {
        if (t < o) {
            const float m2 = sm[t + o], s2 = ss[t + o];
            if (m2 > sm[t]) { ss[t] = ss[t] * __expf(sm[t] - m2) + s2; sm[t] = m2; }
            else            { ss[t] += s2 * __expf(m2 - sm[t]); }
        }
        __syncthreads();
    }
    if (t == 0) g_lse[b] = sm[0] + logf(ss[0]);
}

// ---------------- K4c: finalize out = logit - lse[b] ----------------
__global__ void k_final(float* __restrict__ out) {
    const int i = blockIdx.x * 256 + threadIdx.x;
    if (i >= BATCH * VOCAB / 4) return;
    const int b = (i * 4) / VOCAB;
    const float lse = __ldg(g_lse + b);
    float4 v = ((float4*)out)[i];
    v.x -= lse; v.y -= lse; v.z -= lse; v.w -= lse;
    ((float4*)out)[i] = v;
}

// ---------------- launch ----------------
extern "C" void kernel_launch(void* const* d_in, const int* in_sizes, int n_in,
                              void* d_out, int out_size) {
    const int*   x  = (const int*)d_in[0];
    const int*   q  = (const int*)d_in[1];
    const float* A  = (const float*)d_in[2];
    const float* TA = (const float*)d_in[3];
    const float* TC = (const float*)d_in[4];
    float* out = (float*)d_out;

    k_u0<<<BATCH, EMBED>>>(q, A);
    k_gather<<<dim3(BATCH * STORY / 4, HOPS + 1), 128>>>(x, A, TA, TC);
    k_hops<<<BATCH, EMBED>>>();

    cudaFuncSetAttribute(k_logits, cudaFuncAttributeMaxDynamicSharedMemorySize, SMEM_LOGITS);
    k_logits<<<NBLK_V, 128, SMEM_LOGITS>>>(A + (size_t)HOPS * VOCAB * EMBED, out);

    k_lse<<<BATCH, 256>>>();
    k_final<<<(BATCH * VOCAB / 4 + 255) / 256, 256>>>(out);
}

// round 6
// speedup vs baseline: 1.3152x; 1.0166x over previous
#include <cuda_runtime.h>
#include <cstddef>
#include <cstdint>

#define VOCAB 100000
#define EMBED 128
#define STORY 50
#define SENT  64
#define BATCH 64
#define QLEN  16
#define HOPS  3

#define VT     128
#define NBLK_V ((VOCAB + VT - 1) / VT)   // 782
#define PAD    132

// ---------------- scratch (device globals: allocation-free) ----------------
__device__ float g_u[BATCH * EMBED];
__device__ float g_mw[HOPS][BATCH * STORY * EMBED];
__device__ float g_cs[HOPS][BATCH * STORY * EMBED];
__device__ float g_pmax[BATCH * NBLK_V];
__device__ float g_psum[BATCH * NBLK_V];
__device__ float g_lse[BATCH];

// ---------------- tf32 helpers ----------------
__device__ __forceinline__ uint32_t to_tf32(float x) {
    uint32_t r;
    asm("cvt.rna.tf32.f32 %0, %1;" : "=r"(r) : "f"(x));
    return r;
}
__device__ __forceinline__ void mma_tf32(float d[4], const uint32_t a[4],
                                         uint32_t b0, uint32_t b1) {
    asm volatile(
        "mma.sync.aligned.m16n8k8.row.col.f32.tf32.tf32.f32 "
        "{%0,%1,%2,%3}, {%4,%5,%6,%7}, {%8,%9}, {%0,%1,%2,%3};"
        : "+f"(d[0]), "+f"(d[1]), "+f"(d[2]), "+f"(d[3])
        : "r"(a[0]), "r"(a[1]), "r"(a[2]), "r"(a[3]), "r"(b0), "r"(b1));
}

// ---------------- K1: u0 = sum_j A[0][q[b,j]] ----------------
__global__ void k_u0(const int* __restrict__ q, const float* __restrict__ A) {
    const int b = blockIdx.x;
    const int k = threadIdx.x;   // 128
    float acc = 0.f;
#pragma unroll
    for (int j = 0; j < QLEN; ++j) {
        int idx = __ldg(q + b * QLEN + j);
        acc += __ldg(A + (size_t)idx * EMBED + k);
    }
    g_u[b * EMBED + k] = acc;
}

// ---------------- K2: fused gather-reduce, one warp per (bs,h) ----------------
__global__ void __launch_bounds__(128) k_gather(const int* __restrict__ x,
                                                const float* __restrict__ A,
                                                const float* __restrict__ TA,
                                                const float* __restrict__ TC) {
    const int t    = threadIdx.x;
    const int w    = t >> 5, lane = t & 31;
    const int bs   = blockIdx.x * 4 + w;
    const int h    = blockIdx.y;
    const int s    = bs % STORY;

    __shared__ int idx[4][SENT];
    ((int*)idx)[t]       = x[blockIdx.x * 4 * SENT + t];
    ((int*)idx)[t + 128] = x[blockIdx.x * 4 * SENT + t + 128];
    __syncthreads();

    const float* __restrict__ Ah = A + (size_t)h * VOCAB * EMBED;
    const int c4 = lane * 4;

    const float kf0 = (float)(c4 + 1) * (1.0f / EMBED);
    const float kf1 = (float)(c4 + 2) * (1.0f / EMBED);
    const float kf2 = (float)(c4 + 3) * (1.0f / EMBED);
    const float kf3 = (float)(c4 + 4) * (1.0f / EMBED);

    float4 wp = make_float4(0.f, 0.f, 0.f, 0.f);
    float4 pp = make_float4(0.f, 0.f, 0.f, 0.f);

#pragma unroll 16
    for (int j = 0; j < SENT; ++j) {
        const float4 a = *(const float4*)(Ah + (size_t)idx[w][j] * EMBED + c4);
        const float fj   = (float)(j + 1) * (1.0f / SENT);
        const float g    = 1.0f - 2.0f * fj;
        const float base = 1.0f - fj;
        wp.x = fmaf(a.x, fmaf(-kf0, g, base), wp.x);
        wp.y = fmaf(a.y, fmaf(-kf1, g, base), wp.y);
        wp.z = fmaf(a.z, fmaf(-kf2, g, base), wp.z);
        wp.w = fmaf(a.w, fmaf(-kf3, g, base), wp.w);
        pp.x += a.x; pp.y += a.y; pp.z += a.z; pp.w += a.w;
    }

    if (h < HOPS) {
        const float4 ta4 = *(const float4*)(TA + s * EMBED + c4);
        wp.x += ta4.x; wp.y += ta4.y; wp.z += ta4.z; wp.w += ta4.w;
        *(float4*)(g_mw[h] + (size_t)bs * EMBED + c4) = wp;
    }
    if (h > 0) {
        const float4 tc4 = *(const float4*)(TC + s * EMBED + c4);
        pp.x += tc4.x; pp.y += tc4.y; pp.z += tc4.z; pp.w += tc4.w;
        *(float4*)(g_cs[h - 1] + (size_t)bs * EMBED + c4) = pp;
    }
}

// ---------------- K3: 3 hops, per-batch independent ----------------
__global__ void k_hops() {
    const int b = blockIdx.x;
    const int t = threadIdx.x;     // 128
    const int w = t >> 5, lane = t & 31;

    __shared__ float u[EMBED];
    __shared__ float sc[STORY];

    u[t] = g_u[b * EMBED + t];
    __syncthreads();

    for (int h = 0; h < HOPS; ++h) {
        const float* __restrict__ m = g_mw[h] + (size_t)b * STORY * EMBED;
        const float* __restrict__ c = g_cs[h] + (size_t)b * STORY * EMBED;

        for (int s = w; s < STORY; s += 4) {
            const float* mr = m + s * EMBED;
            float d = mr[lane]      * u[lane]
                    + mr[lane + 32] * u[lane + 32]
                    + mr[lane + 64] * u[lane + 64]
                    + mr[lane + 96] * u[lane + 96];
#pragma unroll
            for (int o = 16; o; o >>= 1) d += __shfl_xor_sync(0xffffffffu, d, o);
            if (lane == 0) sc[s] = d;
        }
        __syncthreads();

        if (t < 32) {
            float v0 = sc[t];
            float v1 = (t + 32 < STORY) ? sc[t + 32] : -3.4e38f;
            float mx = fmaxf(v0, v1);
#pragma unroll
            for (int o = 16; o; o >>= 1) mx = fmaxf(mx, __shfl_xor_sync(0xffffffffu, mx, o));
            float e0 = __expf(v0 - mx);
            float e1 = (t + 32 < STORY) ? __expf(v1 - mx) : 0.f;
            float sum = e0 + e1;
#pragma unroll
            for (int o = 16; o; o >>= 1) sum += __shfl_xor_sync(0xffffffffu, sum, o);
            float inv = 1.0f / sum;
            sc[t] = e0 * inv;
            if (t + 32 < STORY) sc[t + 32] = e1 * inv;
        }
        __syncthreads();

        float acc = u[t];
        for (int s = 0; s < STORY; ++s)
            acc = fmaf(sc[s], c[s * EMBED + t], acc);
        u[t] = acc;
        __syncthreads();
    }
    g_u[b * EMBED + t] = u[t];
}

// ---------------- K4a: logits via mma.sync tf32 (HMMA) ----------------
// Block: 256 threads (8 warps). Tile: VT=128 v x 64 b, K=128.
// Warp tile: 32 b (wb = wid>>2) x 32 v (wv = wid&3): 2 m-tiles x 4 n-tiles.
// smem: sU[64][132], sA[128][132], redm[4][64], reds[4][64] -> 103424 B, 2 CTA/SM.
#define SU_F  (BATCH * PAD)           // 8448
#define SA_F  (VT * PAD)              // 16896
#define SMEM_LOGITS ((SU_F + SA_F + 512) * 4)   // 103424

__global__ void __launch_bounds__(256, 2) k_logits(const float* __restrict__ A3,
                                                   float* __restrict__ out) {
    extern __shared__ float sh[];
    float* sU   = sh;
    float* sA   = sh + SU_F;
    float* redm = sh + SU_F + SA_F;     // [4][64]
    float* reds = redm + 256;           // [4][64]

    const int t = threadIdx.x, wid = t >> 5, lane = t & 31;
    const int g = lane >> 2, t4 = lane & 3;
    const int wv = wid & 3, wb = wid >> 2;
    const int blk = blockIdx.x, v0 = blk * VT;

    // ---- load tiles, converting to tf32 (rna) once ----
    const float4* srcU = (const float4*)g_u;
#pragma unroll
    for (int i = t; i < BATCH * 32; i += 256) {
        const int r = i >> 5, c = i & 31;
        const float4 v = srcU[i];
        uint4 w = make_uint4(to_tf32(v.x), to_tf32(v.y), to_tf32(v.z), to_tf32(v.w));
        *(uint4*)(sU + r * PAD + c * 4) = w;
    }
    const float4* srcA = (const float4*)A3;
#pragma unroll
    for (int i = t; i < VT * 32; i += 256) {
        const int r = i >> 5, c = i & 31;
        int row = v0 + r; if (row > VOCAB - 1) row = VOCAB - 1;
        const float4 v = srcA[(size_t)row * 32 + c];
        uint4 w = make_uint4(to_tf32(v.x), to_tf32(v.y), to_tf32(v.z), to_tf32(v.w));
        *(uint4*)(sA + r * PAD + c * 4) = w;
    }
    __syncthreads();

    // ---- mainloop ----
    float acc[2][4][4];
#pragma unroll
    for (int m = 0; m < 2; ++m)
#pragma unroll
        for (int n = 0; n < 4; ++n)
#pragma unroll
            for (int e = 0; e < 4; ++e) acc[m][n][e] = 0.f;

    const uint32_t* Ub = (const uint32_t*)sU + (wb * 32 + g) * PAD + t4;
    const uint32_t* Bb = (const uint32_t*)sA + (wv * 32 + g) * PAD + t4;

#pragma unroll 4
    for (int ks = 0; ks < 16; ++ks) {
        const int k0 = ks * 8;
        uint32_t a[2][4];
#pragma unroll
        for (int m = 0; m < 2; ++m) {
            const uint32_t* p = Ub + m * 16 * PAD + k0;
            a[m][0] = p[0];
            a[m][1] = p[8 * PAD];
            a[m][2] = p[4];
            a[m][3] = p[8 * PAD + 4];
        }
#pragma unroll
        for (int n = 0; n < 4; ++n) {
            const uint32_t* p = Bb + n * 8 * PAD + k0;
            const uint32_t b0 = p[0], b1 = p[4];
            mma_tf32(acc[0][n], a[0], b0, b1);
            mma_tf32(acc[1][n], a[1], b0, b1);
        }
    }

    // ---- store logits (float2, v-contiguous) ----
#pragma unroll
    for (int m = 0; m < 2; ++m) {
        const int b0r = wb * 32 + m * 16 + g;
#pragma unroll
        for (int n = 0; n < 4; ++n) {
            const int vv = v0 + wv * 32 + n * 8 + t4 * 2;
            if (vv < VOCAB) {
                *(float2*)(out + (size_t)b0r * VOCAB + vv) =
                    make_float2(acc[m][n][0], acc[m][n][1]);
                *(float2*)(out + (size_t)(b0r + 8) * VOCAB + vv) =
                    make_float2(acc[m][n][2], acc[m][n][3]);
            }
        }
    }

    // ---- per-b per-warp max over this warp's 32 v ----
#pragma unroll
    for (int m = 0; m < 2; ++m)
#pragma unroll
        for (int half = 0; half < 2; ++half) {
            float mx = -3.4e38f;
#pragma unroll
            for (int n = 0; n < 4; ++n) {
                const int vv = v0 + wv * 32 + n * 8 + t4 * 2;
                if (vv < VOCAB)
                    mx = fmaxf(mx, fmaxf(acc[m][n][half * 2], acc[m][n][half * 2 + 1]));
            }
            mx = fmaxf(mx, __shfl_xor_sync(0xffffffffu, mx, 1));
            mx = fmaxf(mx, __shfl_xor_sync(0xffffffffu, mx, 2));
            if (t4 == 0) redm[wv * 64 + wb * 32 + m * 16 + half * 8 + g] = mx;
        }
    __syncthreads();

    // ---- per-b sumexp against block max ----
#pragma unroll
    for (int m = 0; m < 2; ++m)
#pragma unroll
        for (int half = 0; half < 2; ++half) {
            const int bb = wb * 32 + m * 16 + half * 8 + g;
            const float bm = fmaxf(fmaxf(redm[bb], redm[64 + bb]),
                                   fmaxf(redm[128 + bb], redm[192 + bb]));
            float e = 0.f;
#pragma unroll
            for (int n = 0; n < 4; ++n) {
                const int vv = v0 + wv * 32 + n * 8 + t4 * 2;
                if (vv < VOCAB)
                    e += __expf(acc[m][n][half * 2] - bm) +
                         __expf(acc[m][n][half * 2 + 1] - bm);
            }
            e += __shfl_xor_sync(0xffffffffu, e, 1);
            e += __shfl_xor_sync(0xffffffffu, e, 2);
            if (t4 == 0) reds[wv * 64 + bb] = e;
        }
    __syncthreads();

    if (t < BATCH) {
        const float bm = fmaxf(fmaxf(redm[t], redm[64 + t]),
                               fmaxf(redm[128 + t], redm[192 + t]));
        const float bs = reds[t] + reds[64 + t] + reds[128 + t] + reds[192 + t];
        g_pmax[t * NBLK_V + blk] = bm;
        g_psum[t * NBLK_V + blk] = bs;
    }
}

// ---------------- K4b: per-row logsumexp reduce ----------------
__global__ void k_lse() {
    const int b = blockIdx.x, t = threadIdx.x;   // 256
    float m = -3.4e38f, s = 0.f;
    for (int i = t; i < NBLK_V; i += 256) {
        const float bm = g_pmax[b * NBLK_V + i];
        const float bs = g_psum[b * NBLK_V + i];
        if (bm > m) { s = s * __expf(m - bm) + bs; m = bm; }
        else        { s += bs * __expf(bm - m); }
    }
    __shared__ float sm[256], ss[256];
    sm[t] = m; ss[t] = s;
    __syncthreads();
    for (int o = 128; o; o >>= 1) {
        if (t < o) {
            const float m2 = sm[t + o], s2 = ss[t + o];
            if (m2 > sm[t]) { ss[t] = ss[t] * __expf(sm[t] - m2) + s2; sm[t] = m2; }
            else            { ss[t] += s2 * __expf(m2 - sm[t]); }
        }
        __syncthreads();
    }
    if (t == 0) g_lse[b] = sm[0] + logf(ss[0]);
}

// ---------------- K4c: finalize out = logit - lse[b] ----------------
__global__ void k_final(float* __restrict__ out) {
    const int i = blockIdx.x * 256 + threadIdx.x;
    if (i >= BATCH * VOCAB / 4) return;
    const int b = (i * 4) / VOCAB;
    const float lse = __ldg(g_lse + b);
    float4 v = ((float4*)out)[i];
    v.x -= lse; v.y -= lse; v.z -= lse; v.w -= lse;
    ((float4*)out)[i] = v;
}

// ---------------- launch ----------------
extern "C" void kernel_launch(void* const* d_in, const int* in_sizes, int n_in,
                              void* d_out, int out_size) {
    const int*   x  = (const int*)d_in[0];
    const int*   q  = (const int*)d_in[1];
    const float* A  = (const float*)d_in[2];
    const float* TA = (const float*)d_in[3];
    const float* TC = (const float*)d_in[4];
    float* out = (float*)d_out;

    k_u0<<<BATCH, EMBED>>>(q, A);
    k_gather<<<dim3(BATCH * STORY / 4, HOPS + 1), 128>>>(x, A, TA, TC);
    k_hops<<<BATCH, EMBED>>>();

    cudaFuncSetAttribute(k_logits, cudaFuncAttributeMaxDynamicSharedMemorySize, SMEM_LOGITS);
    k_logits<<<NBLK_V, 256, SMEM_LOGITS>>>(A + (size_t)HOPS * VOCAB * EMBED, out);

    k_lse<<<BATCH, 256>>>();
    k_final<<<(BATCH * VOCAB / 4 + 255) / 256, 256>>>(out);
}

// round 7
// speedup vs baseline: 1.3203x; 1.0039x over previous
#include <cuda_runtime.h>
#include <cstddef>
#include <cstdint>

#define VOCAB 100000
#define EMBED 128
#define STORY 50
#define SENT  64
#define BATCH 64
#define QLEN  16
#define HOPS  3

#define VT     128
#define NBLK_V ((VOCAB + VT - 1) / VT)   // 782
#define PAD    132
#define PADK   68
#define GRID_L 304

// ---------------- scratch (device globals: allocation-free) ----------------
__device__ float g_u[BATCH * EMBED];
__device__ float g_mw[HOPS][BATCH * STORY * EMBED];
__device__ float g_cs[HOPS][BATCH * STORY * EMBED];
__device__ float g_pmax[BATCH * NBLK_V];
__device__ float g_psum[BATCH * NBLK_V];
__device__ float g_lse[BATCH];

// ---------------- mma + cp.async helpers ----------------
__device__ __forceinline__ void mma_tf32(float d[4], const uint32_t a[4],
                                         uint32_t b0, uint32_t b1) {
    asm volatile(
        "mma.sync.aligned.m16n8k8.row.col.f32.tf32.tf32.f32 "
        "{%0,%1,%2,%3}, {%4,%5,%6,%7}, {%8,%9}, {%0,%1,%2,%3};"
        : "+f"(d[0]), "+f"(d[1]), "+f"(d[2]), "+f"(d[3])
        : "r"(a[0]), "r"(a[1]), "r"(a[2]), "r"(a[3]), "r"(b0), "r"(b1));
}
__device__ __forceinline__ void cp16(uint32_t dst, const void* src) {
    asm volatile("cp.async.cg.shared.global [%0], [%1], 16;" :: "r"(dst), "l"(src));
}
#define CP_COMMIT() asm volatile("cp.async.commit_group;" ::: "memory")
#define CP_WAIT1()  asm volatile("cp.async.wait_group 1;" ::: "memory")

// ---------------- K1: u0 = sum_j A[0][q[b,j]] ----------------
__global__ void k_u0(const int* __restrict__ q, const float* __restrict__ A) {
    const int b = blockIdx.x;
    const int k = threadIdx.x;   // 128
    float acc = 0.f;
#pragma unroll
    for (int j = 0; j < QLEN; ++j) {
        int idx = __ldg(q + b * QLEN + j);
        acc += __ldg(A + (size_t)idx * EMBED + k);
    }
    g_u[b * EMBED + k] = acc;
}

// ---------------- K2: fused gather-reduce, one warp per (bs,h) ----------------
__global__ void __launch_bounds__(128) k_gather(const int* __restrict__ x,
                                                const float* __restrict__ A,
                                                const float* __restrict__ TA,
                                                const float* __restrict__ TC) {
    const int t    = threadIdx.x;
    const int w    = t >> 5, lane = t & 31;
    const int bs   = blockIdx.x * 4 + w;
    const int h    = blockIdx.y;
    const int s    = bs % STORY;

    __shared__ int idx[4][SENT];
    ((int*)idx)[t]       = x[blockIdx.x * 4 * SENT + t];
    ((int*)idx)[t + 128] = x[blockIdx.x * 4 * SENT + t + 128];
    __syncthreads();

    const float* __restrict__ Ah = A + (size_t)h * VOCAB * EMBED;
    const int c4 = lane * 4;

    const float kf0 = (float)(c4 + 1) * (1.0f / EMBED);
    const float kf1 = (float)(c4 + 2) * (1.0f / EMBED);
    const float kf2 = (float)(c4 + 3) * (1.0f / EMBED);
    const float kf3 = (float)(c4 + 4) * (1.0f / EMBED);

    float4 wp = make_float4(0.f, 0.f, 0.f, 0.f);
    float4 pp = make_float4(0.f, 0.f, 0.f, 0.f);

#pragma unroll 16
    for (int j = 0; j < SENT; ++j) {
        const float4 a = *(const float4*)(Ah + (size_t)idx[w][j] * EMBED + c4);
        const float fj   = (float)(j + 1) * (1.0f / SENT);
        const float g    = 1.0f - 2.0f * fj;
        const float base = 1.0f - fj;
        wp.x = fmaf(a.x, fmaf(-kf0, g, base), wp.x);
        wp.y = fmaf(a.y, fmaf(-kf1, g, base), wp.y);
        wp.z = fmaf(a.z, fmaf(-kf2, g, base), wp.z);
        wp.w = fmaf(a.w, fmaf(-kf3, g, base), wp.w);
        pp.x += a.x; pp.y += a.y; pp.z += a.z; pp.w += a.w;
    }

    if (h < HOPS) {
        const float4 ta4 = *(const float4*)(TA + s * EMBED + c4);
        wp.x += ta4.x; wp.y += ta4.y; wp.z += ta4.z; wp.w += ta4.w;
        *(float4*)(g_mw[h] + (size_t)bs * EMBED + c4) = wp;
    }
    if (h > 0) {
        const float4 tc4 = *(const float4*)(TC + s * EMBED + c4);
        pp.x += tc4.x; pp.y += tc4.y; pp.z += tc4.z; pp.w += tc4.w;
        *(float4*)(g_cs[h - 1] + (size_t)bs * EMBED + c4) = pp;
    }
}

// ---------------- K3: 3 hops, per-batch independent ----------------
__global__ void k_hops() {
    const int b = blockIdx.x;
    const int t = threadIdx.x;     // 128
    const int w = t >> 5, lane = t & 31;

    __shared__ float u[EMBED];
    __shared__ float sc[STORY];

    u[t] = g_u[b * EMBED + t];
    __syncthreads();

    for (int h = 0; h < HOPS; ++h) {
        const float* __restrict__ m = g_mw[h] + (size_t)b * STORY * EMBED;
        const float* __restrict__ c = g_cs[h] + (size_t)b * STORY * EMBED;

        for (int s = w; s < STORY; s += 4) {
            const float* mr = m + s * EMBED;
            float d = mr[lane]      * u[lane]
                    + mr[lane + 32] * u[lane + 32]
                    + mr[lane + 64] * u[lane + 64]
                    + mr[lane + 96] * u[lane + 96];
#pragma unroll
            for (int o = 16; o; o >>= 1) d += __shfl_xor_sync(0xffffffffu, d, o);
            if (lane == 0) sc[s] = d;
        }
        __syncthreads();

        if (t < 32) {
            float v0 = sc[t];
            float v1 = (t + 32 < STORY) ? sc[t + 32] : -3.4e38f;
            float mx = fmaxf(v0, v1);
#pragma unroll
            for (int o = 16; o; o >>= 1) mx = fmaxf(mx, __shfl_xor_sync(0xffffffffu, mx, o));
            float e0 = __expf(v0 - mx);
            float e1 = (t + 32 < STORY) ? __expf(v1 - mx) : 0.f;
            float sum = e0 + e1;
#pragma unroll
            for (int o = 16; o; o >>= 1) sum += __shfl_xor_sync(0xffffffffu, sum, o);
            float inv = 1.0f / sum;
            sc[t] = e0 * inv;
            if (t + 32 < STORY) sc[t + 32] = e1 * inv;
        }
        __syncthreads();

        float acc = u[t];
        for (int s = 0; s < STORY; ++s)
            acc = fmaf(sc[s], c[s * EMBED + t], acc);
        u[t] = acc;
        __syncthreads();
    }
    g_u[b * EMBED + t] = u[t];
}

// ---------------- K4a: persistent tf32-HMMA logits, cp.async pipelined ----------------
// Grid 304 (2/SM). Each block: tiles blk, blk+304, ... Per tile 2 k-chunks of 64.
// smem floats: sU[64][132]=8448, sA 2x[128][68]=17408, red 512 -> 105472 B.
#define SU_F   (BATCH * PAD)           // 8448
#define SAC_F  (VT * PADK)             // 8704
#define RED_O  (SU_F + 2 * SAC_F)      // 25856
#define SMEM_LOGITS ((RED_O + 512) * 4)   // 105472

__global__ void __launch_bounds__(256, 2) k_logits(const float* __restrict__ A3,
                                                   float* __restrict__ out) {
    extern __shared__ float sh[];
    float* sU   = sh;
    float* redm = sh + RED_O;           // [4][64]
    float* reds = redm + 256;           // [4][64]

    const int t = threadIdx.x, wid = t >> 5, lane = t & 31;
    const int g = lane >> 2, t4 = lane & 3;
    const int wv = wid & 3, wb = wid >> 2;
    const int blk = blockIdx.x;

    const uint32_t smem_b = (uint32_t)__cvta_generic_to_shared(sh);
    const uint32_t sU_b   = smem_b;
    const uint32_t sA_b   = smem_b + SU_F * 4;

    int ntiles = 0;
    for (int tile = blk; tile < NBLK_V; tile += GRID_L) ++ntiles;
    if (ntiles == 0) return;
    const int S = ntiles * 2;

    // ---- prefetch helpers ----
    // A chunk: 2048 cp16 (8/thread). i = t + 256*it: row = i>>4, col = i&15.
    auto prefA = [&](int buf, int s) {
        const int tile = blk + (s >> 1) * GRID_L;
        const int v0 = tile * VT, c = (s & 1) * 64;
        const uint32_t dst0 = sA_b + buf * (SAC_F * 4);
#pragma unroll
        for (int it = 0; it < 8; ++it) {
            const int i = t + it * 256;
            const int row = i >> 4, col = i & 15;
            int gr = v0 + row; if (gr > VOCAB - 1) gr = VOCAB - 1;
            cp16(dst0 + (row * PADK + col * 4) * 4,
                 A3 + (size_t)gr * EMBED + c + col * 4);
        }
    };

    // group 0: sU (2048 cp16) + chunk 0
#pragma unroll
    for (int it = 0; it < 8; ++it) {
        const int i = t + it * 256;
        const int row = i >> 5, col = i & 31;
        cp16(sU_b + (row * PAD + col * 4) * 4, g_u + row * EMBED + col * 4);
    }
    prefA(0, 0);
    CP_COMMIT();
    if (S > 1) { prefA(1, 1); }
    CP_COMMIT();

    float acc[2][4][4];
#pragma unroll
    for (int m = 0; m < 2; ++m)
#pragma unroll
        for (int n = 0; n < 4; ++n)
#pragma unroll
            for (int e = 0; e < 4; ++e) acc[m][n][e] = 0.f;

    const uint32_t* Ub = (const uint32_t*)sU + (wb * 32 + g) * PAD + t4;

    for (int s = 0; s < S; ++s) {
        CP_WAIT1();
        __syncthreads();

        const int buf = s & 1, ksel = s & 1;
        const uint32_t* Bb = (const uint32_t*)(sh + SU_F + buf * SAC_F)
                           + (wv * 32 + g) * PADK + t4;
        const int kofs = ksel * 64;

#pragma unroll
        for (int ks = 0; ks < 8; ++ks) {
            const int k0 = ks * 8;
            uint32_t a[2][4];
#pragma unroll
            for (int m = 0; m < 2; ++m) {
                const uint32_t* p = Ub + m * 16 * PAD + kofs + k0;
                a[m][0] = p[0];
                a[m][1] = p[8 * PAD];
                a[m][2] = p[4];
                a[m][3] = p[8 * PAD + 4];
            }
#pragma unroll
            for (int n = 0; n < 4; ++n) {
                const uint32_t* p = Bb + n * 8 * PADK + k0;
                const uint32_t b0 = p[0], b1 = p[4];
                mma_tf32(acc[0][n], a[0], b0, b1);
                mma_tf32(acc[1][n], a[1], b0, b1);
            }
        }
        __syncthreads();

        if (s + 2 < S) prefA(buf, s + 2);
        CP_COMMIT();

        if (s & 1) {
            // ---- tile epilogue ----
            const int tile = blk + (s >> 1) * GRID_L;
            const int v0 = tile * VT;

#pragma unroll
            for (int m = 0; m < 2; ++m) {
                const int b0r = wb * 32 + m * 16 + g;
#pragma unroll
                for (int n = 0; n < 4; ++n) {
                    const int vv = v0 + wv * 32 + n * 8 + t4 * 2;
                    if (vv < VOCAB) {
                        *(float2*)(out + (size_t)b0r * VOCAB + vv) =
                            make_float2(acc[m][n][0], acc[m][n][1]);
                        *(float2*)(out + (size_t)(b0r + 8) * VOCAB + vv) =
                            make_float2(acc[m][n][2], acc[m][n][3]);
                    }
                }
            }

#pragma unroll
            for (int m = 0; m < 2; ++m)
#pragma unroll
                for (int half = 0; half < 2; ++half) {
                    float mx = -3.4e38f;
#pragma unroll
                    for (int n = 0; n < 4; ++n) {
                        const int vv = v0 + wv * 32 + n * 8 + t4 * 2;
                        if (vv < VOCAB)
                            mx = fmaxf(mx, fmaxf(acc[m][n][half * 2],
                                                 acc[m][n][half * 2 + 1]));
                    }
                    mx = fmaxf(mx, __shfl_xor_sync(0xffffffffu, mx, 1));
                    mx = fmaxf(mx, __shfl_xor_sync(0xffffffffu, mx, 2));
                    if (t4 == 0) redm[wv * 64 + wb * 32 + m * 16 + half * 8 + g] = mx;
                }
            __syncthreads();

#pragma unroll
            for (int m = 0; m < 2; ++m)
#pragma unroll
                for (int half = 0; half < 2; ++half) {
                    const int bb = wb * 32 + m * 16 + half * 8 + g;
                    const float bm = fmaxf(fmaxf(redm[bb], redm[64 + bb]),
                                           fmaxf(redm[128 + bb], redm[192 + bb]));
                    float e = 0.f;
#pragma unroll
                    for (int n = 0; n < 4; ++n) {
                        const int vv = v0 + wv * 32 + n * 8 + t4 * 2;
                        if (vv < VOCAB)
                            e += __expf(acc[m][n][half * 2] - bm) +
                                 __expf(acc[m][n][half * 2 + 1] - bm);
                    }
                    e += __shfl_xor_sync(0xffffffffu, e, 1);
                    e += __shfl_xor_sync(0xffffffffu, e, 2);
                    if (t4 == 0) reds[wv * 64 + bb] = e;
                }
            __syncthreads();

            if (t < BATCH) {
                const float bm = fmaxf(fmaxf(redm[t], redm[64 + t]),
                                       fmaxf(redm[128 + t], redm[192 + t]));
                const float bs = reds[t] + reds[64 + t] + reds[128 + t] + reds[192 + t];
                g_pmax[t * NBLK_V + tile] = bm;
                g_psum[t * NBLK_V + tile] = bs;
            }
            __syncthreads();

#pragma unroll
            for (int m = 0; m < 2; ++m)
#pragma unroll
                for (int n = 0; n < 4; ++n)
#pragma unroll
                    for (int e = 0; e < 4; ++e) acc[m][n][e] = 0.f;
        }
    }
}

// ---------------- K4b: per-row logsumexp reduce ----------------
__global__ void k_lse() {
    const int b = blockIdx.x, t = threadIdx.x;   // 256
    float m = -3.4e38f, s = 0.f;
    for (int i = t; i < NBLK_V; i += 256) {
        const float bm = g_pmax[b * NBLK_V + i];
        const float bs = g_psum[b * NBLK_V + i];
        if (bm > m) { s = s * __expf(m - bm) + bs; m = bm; }
        else        { s += bs * __expf(bm - m); }
    }
    __shared__ float sm[256], ss[256];
    sm[t] = m; ss[t] = s;
    __syncthreads();
    for (int o = 128; o; o >>= 1) {
        if (t < o) {
            const float m2 = sm[t + o], s2 = ss[t + o];
            if (m2 > sm[t]) { ss[t] = ss[t] * __expf(sm[t] - m2) + s2; sm[t] = m2; }
            else            { ss[t] += s2 * __expf(m2 - sm[t]); }
        }
        __syncthreads();
    }
    if (t == 0) g_lse[b] = sm[0] + logf(ss[0]);
}

// ---------------- K4c: finalize out = logit - lse[b] ----------------
__global__ void k_final(float* __restrict__ out) {
    const int i = blockIdx.x * 256 + threadIdx.x;
    if (i >= BATCH * VOCAB / 4) return;
    const int b = (i * 4) / VOCAB;
    const float lse = __ldg(g_lse + b);
    float4 v = ((float4*)out)[i];
    v.x -= lse; v.y -= lse; v.z -= lse; v.w -= lse;
    ((float4*)out)[i] = v;
}

// ---------------- launch ----------------
extern "C" void kernel_launch(void* const* d_in, const int* in_sizes, int n_in,
                              void* d_out, int out_size) {
    const int*   x  = (const int*)d_in[0];
    const int*   q  = (const int*)d_in[1];
    const float* A  = (const float*)d_in[2];
    const float* TA = (const float*)d_in[3];
    const float* TC = (const float*)d_in[4];
    float* out = (float*)d_out;

    k_u0<<<BATCH, EMBED>>>(q, A);
    k_gather<<<dim3(BATCH * STORY / 4, HOPS + 1), 128>>>(x, A, TA, TC);
    k_hops<<<BATCH, EMBED>>>();

    cudaFuncSetAttribute(k_logits, cudaFuncAttributeMaxDynamicSharedMemorySize, SMEM_LOGITS);
    k_logits<<<GRID_L, 256, SMEM_LOGITS>>>(A + (size_t)HOPS * VOCAB * EMBED, out);

    k_lse<<<BATCH, 256>>>();
    k_final<<<(BATCH * VOCAB / 4 + 255) / 256, 256>>>(out);
}

// round 8
// speedup vs baseline: 1.3837x; 1.0480x over previous
#include <cuda_runtime.h>
#include <cstddef>
#include <cstdint>

#define VOCAB 100000
#define EMBED 128
#define STORY 50
#define SENT  64
#define BATCH 64
#define QLEN  16
#define HOPS  3

#define VT     128
#define NBLK_V ((VOCAB + VT - 1) / VT)   // 782
#define PAD    132
#define PADK   68
#define GRID_L 304

// ---------------- scratch (device globals: allocation-free) ----------------
__device__ float g_u[BATCH * EMBED];
__device__ float g_mw[HOPS][BATCH * STORY * EMBED];
__device__ float g_cs[HOPS][BATCH * STORY * EMBED];
__device__ float g_pmax[BATCH * NBLK_V];
__device__ float g_psum[BATCH * NBLK_V];

// ---------------- mma + cp.async helpers ----------------
__device__ __forceinline__ void mma_tf32(float d[4], const uint32_t a[4],
                                         uint32_t b0, uint32_t b1) {
    asm volatile(
        "mma.sync.aligned.m16n8k8.row.col.f32.tf32.tf32.f32 "
        "{%0,%1,%2,%3}, {%4,%5,%6,%7}, {%8,%9}, {%0,%1,%2,%3};"
        : "+f"(d[0]), "+f"(d[1]), "+f"(d[2]), "+f"(d[3])
        : "r"(a[0]), "r"(a[1]), "r"(a[2]), "r"(a[3]), "r"(b0), "r"(b1));
}
__device__ __forceinline__ void cp16(uint32_t dst, const void* src) {
    asm volatile("cp.async.cg.shared.global [%0], [%1], 16;" :: "r"(dst), "l"(src));
}
#define CP_COMMIT() asm volatile("cp.async.commit_group;" ::: "memory")
#define CP_WAIT1()  asm volatile("cp.async.wait_group 1;" ::: "memory")

// ---------------- K2: fused gather-reduce, one warp per (bs,h) ----------------
// 64-reg cap (8 CTAs/SM = full RF) + unroll 8: memory-throughput bound.
__global__ void __launch_bounds__(128, 8) k_gather(const int* __restrict__ x,
                                                   const float* __restrict__ A,
                                                   const float* __restrict__ TA,
                                                   const float* __restrict__ TC) {
    const int t    = threadIdx.x;
    const int w    = t >> 5, lane = t & 31;
    const int bs   = blockIdx.x * 4 + w;
    const int h    = blockIdx.y;
    const int s    = bs % STORY;

    __shared__ int idx[4][SENT];
    ((int*)idx)[t]       = x[blockIdx.x * 4 * SENT + t];
    ((int*)idx)[t + 128] = x[blockIdx.x * 4 * SENT + t + 128];
    __syncthreads();

    const float* __restrict__ Ah = A + (size_t)h * VOCAB * EMBED;
    const int c4 = lane * 4;

    const float kf0 = (float)(c4 + 1) * (1.0f / EMBED);
    const float kf1 = (float)(c4 + 2) * (1.0f / EMBED);
    const float kf2 = (float)(c4 + 3) * (1.0f / EMBED);
    const float kf3 = (float)(c4 + 4) * (1.0f / EMBED);

    float4 wp = make_float4(0.f, 0.f, 0.f, 0.f);
    float4 pp = make_float4(0.f, 0.f, 0.f, 0.f);

#pragma unroll 8
    for (int j = 0; j < SENT; ++j) {
        const float4 a = *(const float4*)(Ah + (size_t)idx[w][j] * EMBED + c4);
        const float fj   = (float)(j + 1) * (1.0f / SENT);
        const float g    = 1.0f - 2.0f * fj;
        const float base = 1.0f - fj;
        wp.x = fmaf(a.x, fmaf(-kf0, g, base), wp.x);
        wp.y = fmaf(a.y, fmaf(-kf1, g, base), wp.y);
        wp.z = fmaf(a.z, fmaf(-kf2, g, base), wp.z);
        wp.w = fmaf(a.w, fmaf(-kf3, g, base), wp.w);
        pp.x += a.x; pp.y += a.y; pp.z += a.z; pp.w += a.w;
    }

    if (h < HOPS) {
        const float4 ta4 = *(const float4*)(TA + s * EMBED + c4);
        wp.x += ta4.x; wp.y += ta4.y; wp.z += ta4.z; wp.w += ta4.w;
        *(float4*)(g_mw[h] + (size_t)bs * EMBED + c4) = wp;
    }
    if (h > 0) {
        const float4 tc4 = *(const float4*)(TC + s * EMBED + c4);
        pp.x += tc4.x; pp.y += tc4.y; pp.z += tc4.z; pp.w += tc4.w;
        *(float4*)(g_cs[h - 1] + (size_t)bs * EMBED + c4) = pp;
    }
}

// ---------------- K3: u0 + 3 hops, per-batch independent ----------------
__global__ void __launch_bounds__(128) k_hops(const int* __restrict__ q,
                                              const float* __restrict__ A) {
    const int b = blockIdx.x;
    const int t = threadIdx.x;     // 128
    const int w = t >> 5, lane = t & 31;

    __shared__ float u[EMBED];
    __shared__ float sc[STORY];

    // u0 = sum_j A[0][q[b,j]]  (fused former k_u0)
    {
        float acc = 0.f;
#pragma unroll
        for (int j = 0; j < QLEN; ++j) {
            const int idx = __ldg(q + b * QLEN + j);
            acc += __ldg(A + (size_t)idx * EMBED + t);
        }
        u[t] = acc;
    }
    __syncthreads();

    for (int h = 0; h < HOPS; ++h) {
        const float* __restrict__ m = g_mw[h] + (size_t)b * STORY * EMBED;
        const float* __restrict__ c = g_cs[h] + (size_t)b * STORY * EMBED;

        for (int s = w; s < STORY; s += 4) {
            const float* mr = m + s * EMBED;
            float d = mr[lane]      * u[lane]
                    + mr[lane + 32] * u[lane + 32]
                    + mr[lane + 64] * u[lane + 64]
                    + mr[lane + 96] * u[lane + 96];
#pragma unroll
            for (int o = 16; o; o >>= 1) d += __shfl_xor_sync(0xffffffffu, d, o);
            if (lane == 0) sc[s] = d;
        }
        __syncthreads();

        if (t < 32) {
            float v0 = sc[t];
            float v1 = (t + 32 < STORY) ? sc[t + 32] : -3.4e38f;
            float mx = fmaxf(v0, v1);
#pragma unroll
            for (int o = 16; o; o >>= 1) mx = fmaxf(mx, __shfl_xor_sync(0xffffffffu, mx, o));
            float e0 = __expf(v0 - mx);
            float e1 = (t + 32 < STORY) ? __expf(v1 - mx) : 0.f;
            float sum = e0 + e1;
#pragma unroll
            for (int o = 16; o; o >>= 1) sum += __shfl_xor_sync(0xffffffffu, sum, o);
            float inv = 1.0f / sum;
            sc[t] = e0 * inv;
            if (t + 32 < STORY) sc[t + 32] = e1 * inv;
        }
        __syncthreads();

        float acc = u[t];
        for (int s = 0; s < STORY; ++s)
            acc = fmaf(sc[s], c[s * EMBED + t], acc);
        u[t] = acc;
        __syncthreads();
    }
    g_u[b * EMBED + t] = u[t];
}

// ---------------- K4a: persistent tf32-HMMA logits, cp.async pipelined ----------------
#define SU_F   (BATCH * PAD)           // 8448
#define SAC_F  (VT * PADK)             // 8704
#define RED_O  (SU_F + 2 * SAC_F)      // 25856
#define SMEM_LOGITS ((RED_O + 512) * 4)   // 105472

__global__ void __launch_bounds__(256, 2) k_logits(const float* __restrict__ A3,
                                                   float* __restrict__ out) {
    extern __shared__ float sh[];
    float* sU   = sh;
    float* redm = sh + RED_O;           // [4][64]
    float* reds = redm + 256;           // [4][64]

    const int t = threadIdx.x, wid = t >> 5, lane = t & 31;
    const int g = lane >> 2, t4 = lane & 3;
    const int wv = wid & 3, wb = wid >> 2;
    const int blk = blockIdx.x;

    const uint32_t smem_b = (uint32_t)__cvta_generic_to_shared(sh);
    const uint32_t sU_b   = smem_b;
    const uint32_t sA_b   = smem_b + SU_F * 4;

    int ntiles = 0;
    for (int tile = blk; tile < NBLK_V; tile += GRID_L) ++ntiles;
    if (ntiles == 0) return;
    const int S = ntiles * 2;

    auto prefA = [&](int buf, int s) {
        const int tile = blk + (s >> 1) * GRID_L;
        const int v0 = tile * VT, c = (s & 1) * 64;
        const uint32_t dst0 = sA_b + buf * (SAC_F * 4);
#pragma unroll
        for (int it = 0; it < 8; ++it) {
            const int i = t + it * 256;
            const int row = i >> 4, col = i & 15;
            int gr = v0 + row; if (gr > VOCAB - 1) gr = VOCAB - 1;
            cp16(dst0 + (row * PADK + col * 4) * 4,
                 A3 + (size_t)gr * EMBED + c + col * 4);
        }
    };

#pragma unroll
    for (int it = 0; it < 8; ++it) {
        const int i = t + it * 256;
        const int row = i >> 5, col = i & 31;
        cp16(sU_b + (row * PAD + col * 4) * 4, g_u + row * EMBED + col * 4);
    }
    prefA(0, 0);
    CP_COMMIT();
    if (S > 1) { prefA(1, 1); }
    CP_COMMIT();

    float acc[2][4][4];
#pragma unroll
    for (int m = 0; m < 2; ++m)
#pragma unroll
        for (int n = 0; n < 4; ++n)
#pragma unroll
            for (int e = 0; e < 4; ++e) acc[m][n][e] = 0.f;

    const uint32_t* Ub = (const uint32_t*)sU + (wb * 32 + g) * PAD + t4;

    for (int s = 0; s < S; ++s) {
        CP_WAIT1();
        __syncthreads();

        const int buf = s & 1, ksel = s & 1;
        const uint32_t* Bb = (const uint32_t*)(sh + SU_F + buf * SAC_F)
                           + (wv * 32 + g) * PADK + t4;
        const int kofs = ksel * 64;

#pragma unroll
        for (int ks = 0; ks < 8; ++ks) {
            const int k0 = ks * 8;
            uint32_t a[2][4];
#pragma unroll
            for (int m = 0; m < 2; ++m) {
                const uint32_t* p = Ub + m * 16 * PAD + kofs + k0;
                a[m][0] = p[0];
                a[m][1] = p[8 * PAD];
                a[m][2] = p[4];
                a[m][3] = p[8 * PAD + 4];
            }
#pragma unroll
            for (int n = 0; n < 4; ++n) {
                const uint32_t* p = Bb + n * 8 * PADK + k0;
                const uint32_t b0 = p[0], b1 = p[4];
                mma_tf32(acc[0][n], a[0], b0, b1);
                mma_tf32(acc[1][n], a[1], b0, b1);
            }
        }
        __syncthreads();

        if (s + 2 < S) prefA(buf, s + 2);
        CP_COMMIT();

        if (s & 1) {
            const int tile = blk + (s >> 1) * GRID_L;
            const int v0 = tile * VT;

#pragma unroll
            for (int m = 0; m < 2; ++m) {
                const int b0r = wb * 32 + m * 16 + g;
#pragma unroll
                for (int n = 0; n < 4; ++n) {
                    const int vv = v0 + wv * 32 + n * 8 + t4 * 2;
                    if (vv < VOCAB) {
                        *(float2*)(out + (size_t)b0r * VOCAB + vv) =
                            make_float2(acc[m][n][0], acc[m][n][1]);
                        *(float2*)(out + (size_t)(b0r + 8) * VOCAB + vv) =
                            make_float2(acc[m][n][2], acc[m][n][3]);
                    }
                }
            }

#pragma unroll
            for (int m = 0; m < 2; ++m)
#pragma unroll
                for (int half = 0; half < 2; ++half) {
                    float mx = -3.4e38f;
#pragma unroll
                    for (int n = 0; n < 4; ++n) {
                        const int vv = v0 + wv * 32 + n * 8 + t4 * 2;
                        if (vv < VOCAB)
                            mx = fmaxf(mx, fmaxf(acc[m][n][half * 2],
                                                 acc[m][n][half * 2 + 1]));
                    }
                    mx = fmaxf(mx, __shfl_xor_sync(0xffffffffu, mx, 1));
                    mx = fmaxf(mx, __shfl_xor_sync(0xffffffffu, mx, 2));
                    if (t4 == 0) redm[wv * 64 + wb * 32 + m * 16 + half * 8 + g] = mx;
                }
            __syncthreads();

#pragma unroll
            for (int m = 0; m < 2; ++m)
#pragma unroll
                for (int half = 0; half < 2; ++half) {
                    const int bb = wb * 32 + m * 16 + half * 8 + g;
                    const float bm = fmaxf(fmaxf(redm[bb], redm[64 + bb]),
                                           fmaxf(redm[128 + bb], redm[192 + bb]));
                    float e = 0.f;
#pragma unroll
                    for (int n = 0; n < 4; ++n) {
                        const int vv = v0 + wv * 32 + n * 8 + t4 * 2;
                        if (vv < VOCAB)
                            e += __expf(acc[m][n][half * 2] - bm) +
                                 __expf(acc[m][n][half * 2 + 1] - bm);
                    }
                    e += __shfl_xor_sync(0xffffffffu, e, 1);
                    e += __shfl_xor_sync(0xffffffffu, e, 2);
                    if (t4 == 0) reds[wv * 64 + bb] = e;
                }
            __syncthreads();

            if (t < BATCH) {
                const float bm = fmaxf(fmaxf(redm[t], redm[64 + t]),
                                       fmaxf(redm[128 + t], redm[192 + t]));
                const float bs = reds[t] + reds[64 + t] + reds[128 + t] + reds[192 + t];
                g_pmax[t * NBLK_V + tile] = bm;
                g_psum[t * NBLK_V + tile] = bs;
            }
            __syncthreads();

#pragma unroll
            for (int m = 0; m < 2; ++m)
#pragma unroll
                for (int n = 0; n < 4; ++n)
#pragma unroll
                    for (int e = 0; e < 4; ++e) acc[m][n][e] = 0.f;
        }
    }
}

// ---------------- K4b: fused lse-reduce + finalize ----------------
// grid (98, 64): block (cx, b) re-reduces row b's 782 partials (L2-hot),
// then applies out[b, cx*1024 .. +1024) -= lse.
__global__ void __launch_bounds__(256) k_final(float* __restrict__ out) {
    const int b = blockIdx.y, t = threadIdx.x;
    float m = -3.4e38f, s = 0.f;
    for (int i = t; i < NBLK_V; i += 256) {
        const float bm = g_pmax[b * NBLK_V + i];
        const float bs = g_psum[b * NBLK_V + i];
        if (bm > m) { s = s * __expf(m - bm) + bs; m = bm; }
        else        { s += bs * __expf(bm - m); }
    }
    __shared__ float sm[256], ss[256];
    sm[t] = m; ss[t] = s;
    __syncthreads();
#pragma unroll
    for (int o = 128; o; o >>= 1) {
        if (t < o) {
            const float m2 = sm[t + o], s2 = ss[t + o];
            if (m2 > sm[t]) { ss[t] = ss[t] * __expf(sm[t] - m2) + s2; sm[t] = m2; }
            else            { ss[t] += s2 * __expf(m2 - sm[t]); }
        }
        __syncthreads();
    }
    __shared__ float lse_s;
    if (t == 0) lse_s = sm[0] + logf(ss[0]);
    __syncthreads();
    const float lse = lse_s;

    const int i4 = blockIdx.x * 256 + t;          // float4 index within row
    if (i4 < VOCAB / 4) {
        float4* p = (float4*)(out + (size_t)b * VOCAB) + i4;
        float4 v = *p;
        v.x -= lse; v.y -= lse; v.z -= lse; v.w -= lse;
        *p = v;
    }
}

// ---------------- launch ----------------
extern "C" void kernel_launch(void* const* d_in, const int* in_sizes, int n_in,
                              void* d_out, int out_size) {
    const int*   x  = (const int*)d_in[0];
    const int*   q  = (const int*)d_in[1];
    const float* A  = (const float*)d_in[2];
    const float* TA = (const float*)d_in[3];
    const float* TC = (const float*)d_in[4];
    float* out = (float*)d_out;

    k_gather<<<dim3(BATCH * STORY / 4, HOPS + 1), 128>>>(x, A, TA, TC);
    k_hops<<<BATCH, 128>>>(q, A);

    cudaFuncSetAttribute(k_logits, cudaFuncAttributeMaxDynamicSharedMemorySize, SMEM_LOGITS);
    k_logits<<<GRID_L, 256, SMEM_LOGITS>>>(A + (size_t)HOPS * VOCAB * EMBED, out);

    k_final<<<dim3((VOCAB / 4 + 255) / 256, BATCH), 256>>>(out);
}

// round 9
// speedup vs baseline: 1.4666x; 1.0599x over previous
#include <cuda_runtime.h>
#include <cstddef>
#include <cstdint>

#define VOCAB 100000
#define EMBED 128
#define STORY 50
#define SENT  64
#define BATCH 64
#define QLEN  16
#define HOPS  3

#define VT     128
#define NBLK_V ((VOCAB + VT - 1) / VT)   // 782
#define PAD    132
#define PADK   68
#define GRID_L 304

// ---------------- scratch (device globals: allocation-free) ----------------
__device__ float g_u[BATCH * EMBED];
__device__ float g_mw[HOPS][BATCH * STORY * EMBED];
__device__ float g_cs[HOPS][BATCH * STORY * EMBED];
__device__ float g_pmax[BATCH * NBLK_V];
__device__ float g_psum[BATCH * NBLK_V];
__device__ float g_lse[BATCH];

// ---------------- mma + cp.async helpers ----------------
__device__ __forceinline__ void mma_tf32(float d[4], const uint32_t a[4],
                                         uint32_t b0, uint32_t b1) {
    asm volatile(
        "mma.sync.aligned.m16n8k8.row.col.f32.tf32.tf32.f32 "
        "{%0,%1,%2,%3}, {%4,%5,%6,%7}, {%8,%9}, {%0,%1,%2,%3};"
        : "+f"(d[0]), "+f"(d[1]), "+f"(d[2]), "+f"(d[3])
        : "r"(a[0]), "r"(a[1]), "r"(a[2]), "r"(a[3]), "r"(b0), "r"(b1));
}
__device__ __forceinline__ void cp16(uint32_t dst, const void* src) {
    asm volatile("cp.async.cg.shared.global [%0], [%1], 16;" :: "r"(dst), "l"(src));
}
#define CP_COMMIT() asm volatile("cp.async.commit_group;" ::: "memory")
#define CP_WAIT1()  asm volatile("cp.async.wait_group 1;" ::: "memory")

// ---------------- K2: fused gather-reduce, one warp per (bs,h) ----------------
__global__ void __launch_bounds__(128, 8) k_gather(const int* __restrict__ x,
                                                   const float* __restrict__ A,
                                                   const float* __restrict__ TA,
                                                   const float* __restrict__ TC) {
    const int t    = threadIdx.x;
    const int w    = t >> 5, lane = t & 31;
    const int bs   = blockIdx.x * 4 + w;
    const int h    = blockIdx.y;
    const int s    = bs % STORY;

    __shared__ int idx[4][SENT];
    ((int*)idx)[t]       = x[blockIdx.x * 4 * SENT + t];
    ((int*)idx)[t + 128] = x[blockIdx.x * 4 * SENT + t + 128];
    __syncthreads();

    const float* __restrict__ Ah = A + (size_t)h * VOCAB * EMBED;
    const int c4 = lane * 4;

    const float kf0 = (float)(c4 + 1) * (1.0f / EMBED);
    const float kf1 = (float)(c4 + 2) * (1.0f / EMBED);
    const float kf2 = (float)(c4 + 3) * (1.0f / EMBED);
    const float kf3 = (float)(c4 + 4) * (1.0f / EMBED);

    float4 wp = make_float4(0.f, 0.f, 0.f, 0.f);
    float4 pp = make_float4(0.f, 0.f, 0.f, 0.f);

#pragma unroll 8
    for (int j = 0; j < SENT; ++j) {
        const float4 a = *(const float4*)(Ah + (size_t)idx[w][j] * EMBED + c4);
        const float fj   = (float)(j + 1) * (1.0f / SENT);
        const float g    = 1.0f - 2.0f * fj;
        const float base = 1.0f - fj;
        wp.x = fmaf(a.x, fmaf(-kf0, g, base), wp.x);
        wp.y = fmaf(a.y, fmaf(-kf1, g, base), wp.y);
        wp.z = fmaf(a.z, fmaf(-kf2, g, base), wp.z);
        wp.w = fmaf(a.w, fmaf(-kf3, g, base), wp.w);
        pp.x += a.x; pp.y += a.y; pp.z += a.z; pp.w += a.w;
    }

    if (h < HOPS) {
        const float4 ta4 = *(const float4*)(TA + s * EMBED + c4);
        wp.x += ta4.x; wp.y += ta4.y; wp.z += ta4.z; wp.w += ta4.w;
        *(float4*)(g_mw[h] + (size_t)bs * EMBED + c4) = wp;
    }
    if (h > 0) {
        const float4 tc4 = *(const float4*)(TC + s * EMBED + c4);
        pp.x += tc4.x; pp.y += tc4.y; pp.z += tc4.z; pp.w += tc4.w;
        *(float4*)(g_cs[h - 1] + (size_t)bs * EMBED + c4) = pp;
    }
}

// ---------------- K3: u0 + 3 hops, per-batch independent ----------------
__global__ void __launch_bounds__(128) k_hops(const int* __restrict__ q,
                                              const float* __restrict__ A) {
    const int b = blockIdx.x;
    const int t = threadIdx.x;     // 128
    const int w = t >> 5, lane = t & 31;

    __shared__ float u[EMBED];
    __shared__ float sc[STORY];

    {
        float acc = 0.f;
#pragma unroll
        for (int j = 0; j < QLEN; ++j) {
            const int idx = __ldg(q + b * QLEN + j);
            acc += __ldg(A + (size_t)idx * EMBED + t);
        }
        u[t] = acc;
    }
    __syncthreads();

    for (int h = 0; h < HOPS; ++h) {
        const float* __restrict__ m = g_mw[h] + (size_t)b * STORY * EMBED;
        const float* __restrict__ c = g_cs[h] + (size_t)b * STORY * EMBED;

        for (int s = w; s < STORY; s += 4) {
            const float* mr = m + s * EMBED;
            float d = mr[lane]      * u[lane]
                    + mr[lane + 32] * u[lane + 32]
                    + mr[lane + 64] * u[lane + 64]
                    + mr[lane + 96] * u[lane + 96];
#pragma unroll
            for (int o = 16; o; o >>= 1) d += __shfl_xor_sync(0xffffffffu, d, o);
            if (lane == 0) sc[s] = d;
        }
        __syncthreads();

        if (t < 32) {
            float v0 = sc[t];
            float v1 = (t + 32 < STORY) ? sc[t + 32] : -3.4e38f;
            float mx = fmaxf(v0, v1);
#pragma unroll
            for (int o = 16; o; o >>= 1) mx = fmaxf(mx, __shfl_xor_sync(0xffffffffu, mx, o));
            float e0 = __expf(v0 - mx);
            float e1 = (t + 32 < STORY) ? __expf(v1 - mx) : 0.f;
            float sum = e0 + e1;
#pragma unroll
            for (int o = 16; o; o >>= 1) sum += __shfl_xor_sync(0xffffffffu, sum, o);
            float inv = 1.0f / sum;
            sc[t] = e0 * inv;
            if (t + 32 < STORY) sc[t + 32] = e1 * inv;
        }
        __syncthreads();

        float acc = u[t];
        for (int s = 0; s < STORY; ++s)
            acc = fmaf(sc[s], c[s * EMBED + t], acc);
        u[t] = acc;
        __syncthreads();
    }
    g_u[b * EMBED + t] = u[t];
}

// ---------------- K4a: persistent tf32-HMMA logits, cp.async pipelined ----------------
#define SU_F   (BATCH * PAD)           // 8448
#define SAC_F  (VT * PADK)             // 8704
#define RED_O  (SU_F + 2 * SAC_F)      // 25856
#define SMEM_LOGITS ((RED_O + 512) * 4)   // 105472

__global__ void __launch_bounds__(256, 2) k_logits(const float* __restrict__ A3,
                                                   float* __restrict__ out) {
    extern __shared__ float sh[];
    float* sU   = sh;
    float* redm = sh + RED_O;           // [4][64]
    float* reds = redm + 256;           // [4][64]

    const int t = threadIdx.x, wid = t >> 5, lane = t & 31;
    const int g = lane >> 2, t4 = lane & 3;
    const int wv = wid & 3, wb = wid >> 2;
    const int blk = blockIdx.x;

    const uint32_t smem_b = (uint32_t)__cvta_generic_to_shared(sh);
    const uint32_t sU_b   = smem_b;
    const uint32_t sA_b   = smem_b + SU_F * 4;

    int ntiles = 0;
    for (int tile = blk; tile < NBLK_V; tile += GRID_L) ++ntiles;
    if (ntiles == 0) return;
    const int S = ntiles * 2;

    auto prefA = [&](int buf, int s) {
        const int tile = blk + (s >> 1) * GRID_L;
        const int v0 = tile * VT, c = (s & 1) * 64;
        const uint32_t dst0 = sA_b + buf * (SAC_F * 4);
#pragma unroll
        for (int it = 0; it < 8; ++it) {
            const int i = t + it * 256;
            const int row = i >> 4, col = i & 15;
            int gr = v0 + row; if (gr > VOCAB - 1) gr = VOCAB - 1;
            cp16(dst0 + (row * PADK + col * 4) * 4,
                 A3 + (size_t)gr * EMBED + c + col * 4);
        }
    };

#pragma unroll
    for (int it = 0; it < 8; ++it) {
        const int i = t + it * 256;
        const int row = i >> 5, col = i & 31;
        cp16(sU_b + (row * PAD + col * 4) * 4, g_u + row * EMBED + col * 4);
    }
    prefA(0, 0);
    CP_COMMIT();
    if (S > 1) { prefA(1, 1); }
    CP_COMMIT();

    float acc[2][4][4];
#pragma unroll
    for (int m = 0; m < 2; ++m)
#pragma unroll
        for (int n = 0; n < 4; ++n)
#pragma unroll
            for (int e = 0; e < 4; ++e) acc[m][n][e] = 0.f;

    const uint32_t* Ub = (const uint32_t*)sU + (wb * 32 + g) * PAD + t4;

    for (int s = 0; s < S; ++s) {
        CP_WAIT1();
        __syncthreads();

        const int buf = s & 1, ksel = s & 1;
        const uint32_t* Bb = (const uint32_t*)(sh + SU_F + buf * SAC_F)
                           + (wv * 32 + g) * PADK + t4;
        const int kofs = ksel * 64;

#pragma unroll
        for (int ks = 0; ks < 8; ++ks) {
            const int k0 = ks * 8;
            uint32_t a[2][4];
#pragma unroll
            for (int m = 0; m < 2; ++m) {
                const uint32_t* p = Ub + m * 16 * PAD + kofs + k0;
                a[m][0] = p[0];
                a[m][1] = p[8 * PAD];
                a[m][2] = p[4];
                a[m][3] = p[8 * PAD + 4];
            }
#pragma unroll
            for (int n = 0; n < 4; ++n) {
                const uint32_t* p = Bb + n * 8 * PADK + k0;
                const uint32_t b0 = p[0], b1 = p[4];
                mma_tf32(acc[0][n], a[0], b0, b1);
                mma_tf32(acc[1][n], a[1], b0, b1);
            }
        }
        __syncthreads();

        if (s + 2 < S) prefA(buf, s + 2);
        CP_COMMIT();

        if (s & 1) {
            const int tile = blk + (s >> 1) * GRID_L;
            const int v0 = tile * VT;

#pragma unroll
            for (int m = 0; m < 2; ++m) {
                const int b0r = wb * 32 + m * 16 + g;
#pragma unroll
                for (int n = 0; n < 4; ++n) {
                    const int vv = v0 + wv * 32 + n * 8 + t4 * 2;
                    if (vv < VOCAB) {
                        *(float2*)(out + (size_t)b0r * VOCAB + vv) =
                            make_float2(acc[m][n][0], acc[m][n][1]);
                        *(float2*)(out + (size_t)(b0r + 8) * VOCAB + vv) =
                            make_float2(acc[m][n][2], acc[m][n][3]);
                    }
                }
            }

#pragma unroll
            for (int m = 0; m < 2; ++m)
#pragma unroll
                for (int half = 0; half < 2; ++half) {
                    float mx = -3.4e38f;
#pragma unroll
                    for (int n = 0; n < 4; ++n) {
                        const int vv = v0 + wv * 32 + n * 8 + t4 * 2;
                        if (vv < VOCAB)
                            mx = fmaxf(mx, fmaxf(acc[m][n][half * 2],
                                                 acc[m][n][half * 2 + 1]));
                    }
                    mx = fmaxf(mx, __shfl_xor_sync(0xffffffffu, mx, 1));
                    mx = fmaxf(mx, __shfl_xor_sync(0xffffffffu, mx, 2));
                    if (t4 == 0) redm[wv * 64 + wb * 32 + m * 16 + half * 8 + g] = mx;
                }
            __syncthreads();

#pragma unroll
            for (int m = 0; m < 2; ++m)
#pragma unroll
                for (int half = 0; half < 2; ++half) {
                    const int bb = wb * 32 + m * 16 + half * 8 + g;
                    const float bm = fmaxf(fmaxf(redm[bb], redm[64 + bb]),
                                           fmaxf(redm[128 + bb], redm[192 + bb]));
                    float e = 0.f;
#pragma unroll
                    for (int n = 0; n < 4; ++n) {
                        const int vv = v0 + wv * 32 + n * 8 + t4 * 2;
                        if (vv < VOCAB)
                            e += __expf(acc[m][n][half * 2] - bm) +
                                 __expf(acc[m][n][half * 2 + 1] - bm);
                    }
                    e += __shfl_xor_sync(0xffffffffu, e, 1);
                    e += __shfl_xor_sync(0xffffffffu, e, 2);
                    if (t4 == 0) reds[wv * 64 + bb] = e;
                }
            __syncthreads();

            if (t < BATCH) {
                const float bm = fmaxf(fmaxf(redm[t], redm[64 + t]),
                                       fmaxf(redm[128 + t], redm[192 + t]));
                const float bs = reds[t] + reds[64 + t] + reds[128 + t] + reds[192 + t];
                g_pmax[t * NBLK_V + tile] = bm;
                g_psum[t * NBLK_V + tile] = bs;
            }
            __syncthreads();

#pragma unroll
            for (int m = 0; m < 2; ++m)
#pragma unroll
                for (int n = 0; n < 4; ++n)
#pragma unroll
                    for (int e = 0; e < 4; ++e) acc[m][n][e] = 0.f;
        }
    }
}

// ---------------- K4b: per-row logsumexp reduce (tiny, L2-hot) ----------------
__global__ void __launch_bounds__(256) k_lse() {
    const int b = blockIdx.x, t = threadIdx.x;   // 256
    float m = -3.4e38f, s = 0.f;
    for (int i = t; i < NBLK_V; i += 256) {
        const float bm = g_pmax[b * NBLK_V + i];
        const float bs = g_psum[b * NBLK_V + i];
        if (bm > m) { s = s * __expf(m - bm) + bs; m = bm; }
        else        { s += bs * __expf(bm - m); }
    }
    __shared__ float sm[256], ss[256];
    sm[t] = m; ss[t] = s;
    __syncthreads();
#pragma unroll
    for (int o = 128; o; o >>= 1) {
        if (t < o) {
            const float m2 = sm[t + o], s2 = ss[t + o];
            if (m2 > sm[t]) { ss[t] = ss[t] * __expf(sm[t] - m2) + s2; sm[t] = m2; }
            else            { ss[t] += s2 * __expf(m2 - sm[t]); }
        }
        __syncthreads();
    }
    if (t == 0) g_lse[b] = sm[0] + logf(ss[0]);
}

// ---------------- K4c: finalize out = logit - lse[b] (pure stream) ----------------
__global__ void __launch_bounds__(256) k_final(float* __restrict__ out) {
    const int b  = blockIdx.y;
    const int i4 = blockIdx.x * 256 + threadIdx.x;   // float4 index within row
    if (i4 >= VOCAB / 4) return;
    const float lse = __ldg(g_lse + b);
    float4* p = (float4*)(out + (size_t)b * VOCAB) + i4;
    float4 v = *p;
    v.x -= lse; v.y -= lse; v.z -= lse; v.w -= lse;
    *p = v;
}

// ---------------- launch ----------------
extern "C" void kernel_launch(void* const* d_in, const int* in_sizes, int n_in,
                              void* d_out, int out_size) {
    const int*   x  = (const int*)d_in[0];
    const int*   q  = (const int*)d_in[1];
    const float* A  = (const float*)d_in[2];
    const float* TA = (const float*)d_in[3];
    const float* TC = (const float*)d_in[4];
    float* out = (float*)d_out;

    k_gather<<<dim3(BATCH * STORY / 4, HOPS + 1), 128>>>(x, A, TA, TC);
    k_hops<<<BATCH, 128>>>(q, A);

    cudaFuncSetAttribute(k_logits, cudaFuncAttributeMaxDynamicSharedMemorySize, SMEM_LOGITS);
    k_logits<<<GRID_L, 256, SMEM_LOGITS>>>(A + (size_t)HOPS * VOCAB * EMBED, out);

    k_lse<<<BATCH, 256>>>();
    k_final<<<dim3((VOCAB / 4 + 255) / 256, BATCH), 256>>>(out);
}